// round 5
// baseline (speedup 1.0000x reference)
#include <cuda_runtime.h>
#include <cuda_fp16.h>
#include <math.h>

#define NN 50000
#define NE 100000
#define D  64
#define F  128
#define DD 4096
#define EPSV 1e-5f
#define ECHUNK 25600   // multiple of 128 (GEMM tile rows); 4 chunks cover 102400 >= NE

// ---------------- scratch (static device globals; no runtime alloc) ----------------
// edge @ W_edge stored as fp16, split into 4 symbols of ~210 MB each
__device__ __align__(16) __half g_raw0[(size_t)ECHUNK * DD];
__device__ __align__(16) __half g_raw1[(size_t)ECHUNK * DD];
__device__ __align__(16) __half g_raw2[(size_t)ECHUNK * DD];
__device__ __align__(16) __half g_raw3[(size_t)ECHUNK * DD];

__device__ __forceinline__ __half* raw_row(int e) {
    int c = e / ECHUNK;
    int r = e - c * ECHUNK;
    __half* base = (c == 0) ? g_raw0 : (c == 1) ? g_raw1 : (c == 2) ? g_raw2 : g_raw3;
    return base + (size_t)r * DD;
}

__device__ __align__(16) float g_colsum[DD];
__device__ __align__(16) float g_colsq[DD];
__device__ __align__(16) float g_a[DD];
__device__ __align__(16) float g_c[DD];
__device__ __align__(16) float g_cnt[NN];
__device__ __align__(16) float g_inv[NN];
__device__ __align__(16) float g_agg[NN * D];
__device__ __align__(16) float g_xin[NN * D];
__device__ __align__(16) float g_node[NN * D];
__device__ __align__(16) float g_acc[NN * D];
__device__ __align__(16) float g_gi[(size_t)NN * 3 * D];
__device__ __align__(16) float g_gh[(size_t)NN * 3 * D];

struct alignas(16) H8 { __half2 a, b, c, d; };

// ---------------- zero / count helpers ----------------
__global__ void k_zero_pre() {
    int i = blockIdx.x * 256 + threadIdx.x;
    if (i < DD) { g_colsum[i] = 0.f; g_colsq[i] = 0.f; }
    if (i < NN) g_cnt[i] = 0.f;
}

__global__ void k_zero_agg() {
    int i = blockIdx.x * 256 + threadIdx.x;
    if (i < NN * D) g_agg[i] = 0.f;
}

__global__ void k_count(const int* __restrict__ ei) {
    int e = blockIdx.x * 256 + threadIdx.x;
    if (e < NE) {
        int dst = ei[NE + e];
        atomicAdd(&g_cnt[dst], 1.0f);
    }
}

__global__ void k_inv() {
    int i = blockIdx.x * 256 + threadIdx.x;
    if (i < NN) g_inv[i] = 1.0f / fmaxf(g_cnt[i], 1.0f);
}

// ---------------- big GEMM: raw = edge[NE,128] @ W_edge[128,4096] + col stats ----
// tile 128x128, K-tile 16, 256 threads, 8x8 microtile; fp32 accum, fp16 store
__global__ __launch_bounds__(256) void k_gemm_edge(const float* __restrict__ A,
                                                   const float* __restrict__ B) {
    __shared__ __align__(16) float As[128][16];
    __shared__ __align__(16) float Bs[16][128];
    __shared__ __align__(16) float red[16][128];

    int tid = threadIdx.x;
    int tx = tid & 15, ty = tid >> 4;
    int m0 = blockIdx.y * 128;
    int n0 = blockIdx.x * 128;

    float acc[8][8];
#pragma unroll
    for (int i = 0; i < 8; i++)
#pragma unroll
        for (int j = 0; j < 8; j++) acc[i][j] = 0.f;

#pragma unroll
    for (int k0 = 0; k0 < F; k0 += 16) {
        // load A tile (128 rows x 16 k), zero-fill OOB rows
#pragma unroll
        for (int l = 0; l < 2; l++) {
            int f4 = tid * 2 + l;           // 0..511
            int m = f4 >> 2, c4 = f4 & 3;   // 4 float4 per row
            float4 v = make_float4(0.f, 0.f, 0.f, 0.f);
            if (m0 + m < NE)
                v = *reinterpret_cast<const float4*>(&A[(size_t)(m0 + m) * F + k0 + c4 * 4]);
            *reinterpret_cast<float4*>(&As[m][c4 * 4]) = v;
        }
        // load B tile (16 k x 128 n)
#pragma unroll
        for (int l = 0; l < 2; l++) {
            int f4 = tid * 2 + l;
            int kk = f4 >> 5, c4 = f4 & 31;
            float4 v = *reinterpret_cast<const float4*>(&B[(size_t)(k0 + kk) * DD + n0 + c4 * 4]);
            *reinterpret_cast<float4*>(&Bs[kk][c4 * 4]) = v;
        }
        __syncthreads();
#pragma unroll
        for (int kk = 0; kk < 16; kk++) {
            float a[8], b[8];
#pragma unroll
            for (int i = 0; i < 8; i++) a[i] = As[ty * 8 + i][kk];
            float4 b0 = *reinterpret_cast<float4*>(&Bs[kk][tx * 8]);
            float4 b1 = *reinterpret_cast<float4*>(&Bs[kk][tx * 8 + 4]);
            b[0] = b0.x; b[1] = b0.y; b[2] = b0.z; b[3] = b0.w;
            b[4] = b1.x; b[5] = b1.y; b[6] = b1.z; b[7] = b1.w;
#pragma unroll
            for (int i = 0; i < 8; i++)
#pragma unroll
                for (int j = 0; j < 8; j++) acc[i][j] = fmaf(a[i], b[j], acc[i][j]);
        }
        __syncthreads();
    }

    // epilogue: fp16 store + per-column fp32 sums/sumsq (OOB rows have acc==0)
    float psum[8], psq[8];
#pragma unroll
    for (int j = 0; j < 8; j++) { psum[j] = 0.f; psq[j] = 0.f; }
#pragma unroll
    for (int i = 0; i < 8; i++) {
        int m = m0 + ty * 8 + i;
        if (m < NE) {
            H8 h;
            h.a = __floats2half2_rn(acc[i][0], acc[i][1]);
            h.b = __floats2half2_rn(acc[i][2], acc[i][3]);
            h.c = __floats2half2_rn(acc[i][4], acc[i][5]);
            h.d = __floats2half2_rn(acc[i][6], acc[i][7]);
            *reinterpret_cast<H8*>(raw_row(m) + n0 + tx * 8) = h;
        }
#pragma unroll
        for (int j = 0; j < 8; j++) {
            psum[j] += acc[i][j];
            psq[j]  += acc[i][j] * acc[i][j];
        }
    }
#pragma unroll
    for (int j = 0; j < 8; j++) red[ty][tx * 8 + j] = psum[j];
    __syncthreads();
    if (tid < 128) {
        float s = 0.f;
#pragma unroll
        for (int t = 0; t < 16; t++) s += red[t][tid];
        atomicAdd(&g_colsum[n0 + tid], s);
    }
    __syncthreads();
#pragma unroll
    for (int j = 0; j < 8; j++) red[ty][tx * 8 + j] = psq[j];
    __syncthreads();
    if (tid < 128) {
        float s = 0.f;
#pragma unroll
        for (int t = 0; t < 16; t++) s += red[t][tid];
        atomicAdd(&g_colsq[n0 + tid], s);
    }
}

// ---------------- BN coefficients ----------------
__global__ void k_bncoef(const float* __restrict__ gamma, const float* __restrict__ beta) {
    int i = blockIdx.x * 256 + threadIdx.x;
    if (i < DD) {
        float mu  = g_colsum[i] * (1.0f / NE);
        float var = g_colsq[i] * (1.0f / NE) - mu * mu;
        float a = gamma[i] * rsqrtf(var + EPSV);
        g_a[i] = a;
        g_c[i] = beta[i] - mu * a;
    }
}

// ---------------- message + scatter: agg[dst] += x[src] . (a*raw + c) -------------
// 32 edges / block (4 concurrent x 8 iters), a/c staged in SMEM once per block
__global__ __launch_bounds__(256) void k_msg(const float* __restrict__ x0,
                                             const int* __restrict__ ei,
                                             int first) {
    __shared__ __align__(16) float a_s[DD];
    __shared__ __align__(16) float c_s[DD];
    __shared__ float xs[4][D];

    const float* __restrict__ x = first ? x0 : (const float*)g_node;
    int tid = threadIdx.x;
    for (int i = tid * 4; i < DD; i += 1024) {
        *reinterpret_cast<float4*>(&a_s[i]) = *reinterpret_cast<const float4*>(&g_a[i]);
        *reinterpret_cast<float4*>(&c_s[i]) = *reinterpret_cast<const float4*>(&g_c[i]);
    }
    __syncthreads();

    int sub = tid >> 6, k = tid & 63;
    int ebase = blockIdx.x * 32;

    for (int it = 0; it < 8; it++) {
        int e = ebase + it * 4 + sub;
        bool valid = e < NE;
        int dst = 0;
        if (valid) {
            int src = ei[e];
            dst = ei[NE + e];
            xs[sub][k] = x[src * D + k];
        }
        __syncthreads();
        if (valid) {
            const __half* rp = raw_row(e) + k;
            float acc0 = 0.f, acc1 = 0.f;
#pragma unroll
            for (int d = 0; d < D; d += 2) {
                int i0 = d * 64 + k;
                float r0 = __half2float(rp[d * 64]);
                float r1 = __half2float(rp[(d + 1) * 64]);
                acc0 = fmaf(xs[sub][d],     fmaf(a_s[i0],      r0, c_s[i0]),      acc0);
                acc1 = fmaf(xs[sub][d + 1], fmaf(a_s[i0 + 64], r1, c_s[i0 + 64]), acc1);
            }
            atomicAdd(&g_agg[dst * D + k], acc0 + acc1);
        }
        __syncthreads();
    }
}

// ---------------- node_in = relu(agg/cnt + bias) ----------------
__global__ void k_xin(const float* __restrict__ bias) {
    int i = blockIdx.x * 256 + threadIdx.x;
    if (i < NN * D) {
        float v = fmaf(g_agg[i], g_inv[i >> 6], bias[i & 63]);
        g_xin[i] = fmaxf(v, 0.f);
    }
}

// ---------------- GRU GEMVs: gi = xin@W_ih^T, gh = h@W_hh^T ----------------
// 32 nodes / block, 192 threads (one gate-row each), W rows in registers
__global__ __launch_bounds__(192) void k_grugemm(const float* __restrict__ x0,
                                                 const float* __restrict__ Wih,
                                                 const float* __restrict__ Whh,
                                                 int first) {
    __shared__ float4 xs4[32][16];
    __shared__ float4 hs4[32][16];
    const float* __restrict__ h = first ? x0 : (const float*)g_node;

    int tid = threadIdx.x;
    int base = blockIdx.x * 32;

    for (int f4 = tid; f4 < 512; f4 += 192) {
        int nb = base + (f4 >> 4);
        int c = f4 & 15;
        float4 v = make_float4(0.f, 0.f, 0.f, 0.f), w = v;
        if (nb < NN) {
            v = *reinterpret_cast<const float4*>(&g_xin[nb * D + c * 4]);
            w = *reinterpret_cast<const float4*>(&h[nb * D + c * 4]);
        }
        xs4[f4 >> 4][c] = v;
        hs4[f4 >> 4][c] = w;
    }
    __syncthreads();

    int g = tid;  // 0..191
    int nmax = NN - base; if (nmax > 32) nmax = 32;

    float4 wr[16];
#pragma unroll
    for (int q = 0; q < 16; q++) wr[q] = reinterpret_cast<const float4*>(Wih)[g * 16 + q];
    for (int nn = 0; nn < nmax; nn++) {
        float acc = 0.f;
#pragma unroll
        for (int q = 0; q < 16; q++) {
            float4 xv = xs4[nn][q]; float4 wv = wr[q];
            acc = fmaf(xv.x, wv.x, acc); acc = fmaf(xv.y, wv.y, acc);
            acc = fmaf(xv.z, wv.z, acc); acc = fmaf(xv.w, wv.w, acc);
        }
        g_gi[(size_t)(base + nn) * 192 + g] = acc;
    }
#pragma unroll
    for (int q = 0; q < 16; q++) wr[q] = reinterpret_cast<const float4*>(Whh)[g * 16 + q];
    for (int nn = 0; nn < nmax; nn++) {
        float acc = 0.f;
#pragma unroll
        for (int q = 0; q < 16; q++) {
            float4 xv = hs4[nn][q]; float4 wv = wr[q];
            acc = fmaf(xv.x, wv.x, acc); acc = fmaf(xv.y, wv.y, acc);
            acc = fmaf(xv.z, wv.z, acc); acc = fmaf(xv.w, wv.w, acc);
        }
        g_gh[(size_t)(base + nn) * 192 + g] = acc;
    }
}

// ---------------- GRU gates + output accumulation ----------------
__global__ void k_gates(const float* __restrict__ x0,
                        const float* __restrict__ b_ih,
                        const float* __restrict__ b_hh,
                        int first) {
    int i = blockIdx.x * 256 + threadIdx.x;
    if (i >= NN * D) return;
    int n = i >> 6, j = i & 63;
    size_t o = (size_t)n * 192 + j;

    float ir = g_gi[o]       + b_ih[j];
    float iz = g_gi[o + 64]  + b_ih[64 + j];
    float in = g_gi[o + 128] + b_ih[128 + j];
    float hr = g_gh[o]       + b_hh[j];
    float hz = g_gh[o + 64]  + b_hh[64 + j];
    float hn = g_gh[o + 128] + b_hh[128 + j];

    float r = 1.0f / (1.0f + expf(-(ir + hr)));
    float z = 1.0f / (1.0f + expf(-(iz + hz)));
    float nv = tanhf(fmaf(r, hn, in));

    float hold = first ? x0[i] : g_node[i];
    float hnew = fmaf(z, hold - nv, nv);   // (1-z)*n + z*h

    if (first) g_acc[i] = hold;
    else       g_acc[i] += hold;
    g_node[i] = hnew;
}

// ---------------- out = (node0+node1+node2+node3)/4 + x0 ----------------
__global__ void k_final(const float* __restrict__ x0, float* __restrict__ out) {
    int i = blockIdx.x * 256 + threadIdx.x;
    if (i < NN * D) out[i] = (g_acc[i] + g_node[i]) * 0.25f + x0[i];
}

// ---------------- launcher ----------------
extern "C" void kernel_launch(void* const* d_in, const int* in_sizes, int n_in,
                              void* d_out, int out_size) {
    const float* node   = (const float*)d_in[0];
    const int*   ei     = (const int*)d_in[1];     // int32! (JAX x64 disabled)
    const float* edge   = (const float*)d_in[2];
    const float* W_edge = (const float*)d_in[3];
    const float* gamma  = (const float*)d_in[4];
    const float* beta   = (const float*)d_in[5];
    const float* bias   = (const float*)d_in[6];
    const float* W_ih   = (const float*)d_in[7];
    const float* W_hh   = (const float*)d_in[8];
    const float* b_ih   = (const float*)d_in[9];
    const float* b_hh   = (const float*)d_in[10];
    float* out = (float*)d_out;

    // prep: counts + edge embedding + BN coefficients
    k_zero_pre<<<196, 256>>>();
    k_count<<<(NE + 255) / 256, 256>>>(ei);
    k_inv<<<196, 256>>>();

    dim3 gg(DD / 128, (NE + 127) / 128);
    k_gemm_edge<<<gg, 256>>>(edge, W_edge);
    k_bncoef<<<16, 256>>>(gamma, beta);

    // only 3 propagation steps are needed: out = x0 + mean(node_0..node_3),
    // node_3 is produced by step 2's update; the reference's 4th update is dead.
    int nelem_blocks = (NN * D + 255) / 256;
    for (int s = 0; s < 3; s++) {
        int first = (s == 0) ? 1 : 0;
        k_zero_agg<<<nelem_blocks, 256>>>();
        k_msg<<<(NE + 31) / 32, 256>>>(node, ei, first);
        k_xin<<<nelem_blocks, 256>>>(bias);
        k_grugemm<<<(NN + 31) / 32, 192>>>(node, W_ih, W_hh, first);
        k_gates<<<nelem_blocks, 256>>>(node, b_ih, b_hh, first);
    }
    k_final<<<nelem_blocks, 256>>>(node, out);
}

// round 6
// speedup vs baseline: 1.6593x; 1.6593x over previous
#include <cuda_runtime.h>
#include <cuda_fp16.h>
#include <math.h>
#include <stdint.h>

#define NN 50000
#define NE 100000
#define D  64
#define F  128
#define DD 4096
#define EPSV 1e-5f
#define ECHUNK 25600   // multiple of 128 (GEMM tile rows); 4 chunks cover 102400 >= NE

// ---------------- scratch (static device globals; no runtime alloc) ----------------
// edge @ W_edge stored as fp16, split into 4 symbols of ~210 MB each
__device__ __align__(16) __half g_raw0[(size_t)ECHUNK * DD];
__device__ __align__(16) __half g_raw1[(size_t)ECHUNK * DD];
__device__ __align__(16) __half g_raw2[(size_t)ECHUNK * DD];
__device__ __align__(16) __half g_raw3[(size_t)ECHUNK * DD];

__device__ __forceinline__ __half* raw_row(int e) {
    int c = e / ECHUNK;
    int r = e - c * ECHUNK;
    __half* base = (c == 0) ? g_raw0 : (c == 1) ? g_raw1 : (c == 2) ? g_raw2 : g_raw3;
    return base + (size_t)r * DD;
}

__device__ __align__(16) float g_colsum[DD];
__device__ __align__(16) float g_colsq[DD];
__device__ __align__(16) float g_a[DD];
__device__ __align__(16) float g_c[DD];
__device__ __align__(16) float g_cnt[NN];
__device__ __align__(16) float g_inv[NN];
__device__ __align__(16) float g_agg[NN * D];
__device__ __align__(16) float g_xin[NN * D];
__device__ __align__(16) float g_node[NN * D];
__device__ __align__(16) float g_acc[NN * D];
__device__ __align__(16) float g_gi[(size_t)NN * 3 * D];
__device__ __align__(16) float g_gh[(size_t)NN * 3 * D];

struct alignas(8) H4 { __half2 x, y; };

// ---------------- zero / count helpers ----------------
__global__ void k_zero_pre() {
    int i = blockIdx.x * 256 + threadIdx.x;
    if (i < DD) { g_colsum[i] = 0.f; g_colsq[i] = 0.f; }
    if (i < NN) g_cnt[i] = 0.f;
}

__global__ void k_zero_agg() {
    int i = blockIdx.x * 256 + threadIdx.x;
    if (i < NN * D) g_agg[i] = 0.f;
}

__global__ void k_count(const int* __restrict__ ei) {
    int e = blockIdx.x * 256 + threadIdx.x;
    if (e < NE) atomicAdd(&g_cnt[ei[NE + e]], 1.0f);
}

__global__ void k_inv() {
    int i = blockIdx.x * 256 + threadIdx.x;
    if (i < NN) g_inv[i] = 1.0f / fmaxf(g_cnt[i], 1.0f);
}

// ---------------- tensor-core GEMM helpers ----------------
__device__ __forceinline__ void ldsm_x4(uint32_t& r0, uint32_t& r1, uint32_t& r2, uint32_t& r3,
                                        uint32_t addr) {
    asm volatile("ldmatrix.sync.aligned.m8n8.x4.shared.b16 {%0,%1,%2,%3}, [%4];"
                 : "=r"(r0), "=r"(r1), "=r"(r2), "=r"(r3) : "r"(addr));
}
__device__ __forceinline__ void ldsm_x4_t(uint32_t& r0, uint32_t& r1, uint32_t& r2, uint32_t& r3,
                                          uint32_t addr) {
    asm volatile("ldmatrix.sync.aligned.m8n8.x4.trans.shared.b16 {%0,%1,%2,%3}, [%4];"
                 : "=r"(r0), "=r"(r1), "=r"(r2), "=r"(r3) : "r"(addr));
}
__device__ __forceinline__ void mma16816(float* c, const uint32_t* a, const uint32_t* b) {
    asm volatile(
        "mma.sync.aligned.m16n8k16.row.col.f32.f16.f16.f32 "
        "{%0,%1,%2,%3}, {%4,%5,%6,%7}, {%8,%9}, {%0,%1,%2,%3};"
        : "+f"(c[0]), "+f"(c[1]), "+f"(c[2]), "+f"(c[3])
        : "r"(a[0]), "r"(a[1]), "r"(a[2]), "r"(a[3]), "r"(b[0]), "r"(b[1]));
}

// ---------------- big GEMM: raw = edge[NE,128] @ W_edge[128,4096] + col stats ----
// HMMA m16n8k16, block tile 128x128, BK=64 (2 iters), 8 warps (2m x 4n), 64x32/warp.
// fp32 accum; fp16 store staged through SMEM for coalescing; BN stats in epilogue.
#define AS_STRIDE 72    // halves (144B: 16B-aligned rows, 4-bank rotation -> conflict-free)
#define BS_STRIDE 136   // halves (272B)
#define CS_STRIDE 136
__global__ __launch_bounds__(256) void k_gemm_edge(const float* __restrict__ A,
                                                   const float* __restrict__ B) {
    __shared__ __align__(16) unsigned char sm[35840];
    __half* As = (__half*)sm;               // [128][72]
    __half* Bs = (__half*)(sm + 18432);     // [64][136]
    __half* Cs = (__half*)sm;               // [128][136] (reuses As/Bs after mainloop)
    float* csum = (float*)(sm + 34816);     // [128]
    float* csq  = (float*)(sm + 34816 + 512);

    int tid = threadIdx.x;
    int warp = tid >> 5, lane = tid & 31;
    int wm = warp & 1, wn = warp >> 1;      // 2 (m) x 4 (n)
    int gid = lane >> 2, tig = lane & 3;
    int m0 = blockIdx.y * 128, n0 = blockIdx.x * 128;

    float c[4][4][4];
#pragma unroll
    for (int i = 0; i < 4; i++)
#pragma unroll
        for (int j = 0; j < 4; j++)
#pragma unroll
            for (int q = 0; q < 4; q++) c[i][j][q] = 0.f;

#pragma unroll
    for (int ki = 0; ki < 2; ki++) {
        int k0 = ki * 64;
        // load A tile 128x64 (fp32 -> fp16), zero-fill OOB rows
#pragma unroll
        for (int it = 0; it < 8; it++) {
            int p = it * 1024 + tid * 4;
            int r = p >> 6, cc = p & 63;
            float4 v = make_float4(0.f, 0.f, 0.f, 0.f);
            if (m0 + r < NE)
                v = *reinterpret_cast<const float4*>(&A[(size_t)(m0 + r) * F + k0 + cc]);
            H4 h; h.x = __floats2half2_rn(v.x, v.y); h.y = __floats2half2_rn(v.z, v.w);
            *reinterpret_cast<H4*>(&As[r * AS_STRIDE + cc]) = h;
        }
        // load B tile 64x128
#pragma unroll
        for (int it = 0; it < 8; it++) {
            int p = it * 1024 + tid * 4;
            int r = p >> 7, cc = p & 127;
            float4 v = *reinterpret_cast<const float4*>(&B[(size_t)(k0 + r) * DD + n0 + cc]);
            H4 h; h.x = __floats2half2_rn(v.x, v.y); h.y = __floats2half2_rn(v.z, v.w);
            *reinterpret_cast<H4*>(&Bs[r * BS_STRIDE + cc]) = h;
        }
        __syncthreads();

#pragma unroll
        for (int ks = 0; ks < 4; ks++) {
            uint32_t a[4][4], b[4][2];
#pragma unroll
            for (int mi = 0; mi < 4; mi++) {
                int row = wm * 64 + mi * 16 + (lane & 15);
                int kof = ks * 16 + ((lane >> 4) << 3);
                uint32_t addr = (uint32_t)__cvta_generic_to_shared(&As[row * AS_STRIDE + kof]);
                ldsm_x4(a[mi][0], a[mi][1], a[mi][2], a[mi][3], addr);
            }
#pragma unroll
            for (int hb = 0; hb < 2; hb++) {
                int krow = ks * 16 + (lane & 15);
                int ncol = wn * 32 + hb * 16 + ((lane >> 4) << 3);
                uint32_t addr = (uint32_t)__cvta_generic_to_shared(&Bs[krow * BS_STRIDE + ncol]);
                ldsm_x4_t(b[2 * hb][0], b[2 * hb][1], b[2 * hb + 1][0], b[2 * hb + 1][1], addr);
            }
#pragma unroll
            for (int mi = 0; mi < 4; mi++)
#pragma unroll
                for (int ni = 0; ni < 4; ni++)
                    mma16816(c[mi][ni], a[mi], b[ni]);
        }
        __syncthreads();
    }

    // ---- epilogue: stats (fp32 accumulators) + staged fp16 store ----
    if (tid < 128) { csum[tid] = 0.f; csq[tid] = 0.f; }
    __syncthreads();

    float psum[8], psq[8];
#pragma unroll
    for (int j = 0; j < 8; j++) { psum[j] = 0.f; psq[j] = 0.f; }
#pragma unroll
    for (int mi = 0; mi < 4; mi++) {
#pragma unroll
        for (int ni = 0; ni < 4; ni++) {
            int row0 = wm * 64 + mi * 16 + gid;
            int col = wn * 32 + ni * 8 + tig * 2;
            *reinterpret_cast<__half2*>(&Cs[row0 * CS_STRIDE + col]) =
                __floats2half2_rn(c[mi][ni][0], c[mi][ni][1]);
            *reinterpret_cast<__half2*>(&Cs[(row0 + 8) * CS_STRIDE + col]) =
                __floats2half2_rn(c[mi][ni][2], c[mi][ni][3]);
            psum[ni * 2]     += c[mi][ni][0] + c[mi][ni][2];
            psum[ni * 2 + 1] += c[mi][ni][1] + c[mi][ni][3];
            psq[ni * 2]      += c[mi][ni][0] * c[mi][ni][0] + c[mi][ni][2] * c[mi][ni][2];
            psq[ni * 2 + 1]  += c[mi][ni][1] * c[mi][ni][1] + c[mi][ni][3] * c[mi][ni][3];
        }
    }
#pragma unroll
    for (int ni = 0; ni < 4; ni++) {
#pragma unroll
        for (int t = 0; t < 2; t++) {
            int col = wn * 32 + ni * 8 + tig * 2 + t;
            atomicAdd(&csum[col], psum[ni * 2 + t]);
            atomicAdd(&csq[col],  psq[ni * 2 + t]);
        }
    }
    __syncthreads();

    // coalesced fp16 store: thread -> (row, 64-wide half-row)
    {
        int r = tid >> 1, seg = tid & 1;
        if (m0 + r < NE) {
            __half* dst = raw_row(m0 + r) + n0 + seg * 64;
            const __half* src = &Cs[r * CS_STRIDE + seg * 64];
#pragma unroll
            for (int q = 0; q < 8; q++)
                *reinterpret_cast<uint4*>(&dst[q * 8]) =
                    *reinterpret_cast<const uint4*>(&src[q * 8]);
        }
    }
    if (tid < 128) {
        atomicAdd(&g_colsum[n0 + tid], csum[tid]);
        atomicAdd(&g_colsq[n0 + tid],  csq[tid]);
    }
}

// ---------------- BN coefficients ----------------
__global__ void k_bncoef(const float* __restrict__ gamma, const float* __restrict__ beta) {
    int i = blockIdx.x * 256 + threadIdx.x;
    if (i < DD) {
        float mu  = g_colsum[i] * (1.0f / NE);
        float var = g_colsq[i] * (1.0f / NE) - mu * mu;
        float a = gamma[i] * rsqrtf(var + EPSV);
        g_a[i] = a;
        g_c[i] = beta[i] - mu * a;
    }
}

// ---------------- message + scatter: agg[dst] += x[src] . (a*raw + c) -------------
__global__ __launch_bounds__(256) void k_msg(const float* __restrict__ x0,
                                             const int* __restrict__ ei,
                                             int first) {
    __shared__ __align__(16) float a_s[DD];
    __shared__ __align__(16) float c_s[DD];
    __shared__ float xs[4][D];

    const float* __restrict__ x = first ? x0 : (const float*)g_node;
    int tid = threadIdx.x;
    for (int i = tid * 4; i < DD; i += 1024) {
        *reinterpret_cast<float4*>(&a_s[i]) = *reinterpret_cast<const float4*>(&g_a[i]);
        *reinterpret_cast<float4*>(&c_s[i]) = *reinterpret_cast<const float4*>(&g_c[i]);
    }
    __syncthreads();

    int sub = tid >> 6, k = tid & 63;
    int ebase = blockIdx.x * 32;

    for (int it = 0; it < 8; it++) {
        int e = ebase + it * 4 + sub;
        bool valid = e < NE;
        int dst = 0;
        if (valid) {
            int src = ei[e];
            dst = ei[NE + e];
            xs[sub][k] = x[src * D + k];
        }
        __syncthreads();
        if (valid) {
            const __half* rp = raw_row(e) + k;
            float acc0 = 0.f, acc1 = 0.f;
#pragma unroll
            for (int d = 0; d < D; d += 2) {
                int i0 = d * 64 + k;
                float r0 = __half2float(rp[d * 64]);
                float r1 = __half2float(rp[(d + 1) * 64]);
                acc0 = fmaf(xs[sub][d],     fmaf(a_s[i0],      r0, c_s[i0]),      acc0);
                acc1 = fmaf(xs[sub][d + 1], fmaf(a_s[i0 + 64], r1, c_s[i0 + 64]), acc1);
            }
            atomicAdd(&g_agg[dst * D + k], acc0 + acc1);
        }
        __syncthreads();
    }
}

// ---------------- node_in = relu(agg/cnt + bias) ----------------
__global__ void k_xin(const float* __restrict__ bias) {
    int i = blockIdx.x * 256 + threadIdx.x;
    if (i < NN * D) {
        float v = fmaf(g_agg[i], g_inv[i >> 6], bias[i & 63]);
        g_xin[i] = fmaxf(v, 0.f);
    }
}

// ---------------- GRU GEMVs: gi = xin@W_ih^T, gh = h@W_hh^T ----------------
__global__ __launch_bounds__(192) void k_grugemm(const float* __restrict__ x0,
                                                 const float* __restrict__ Wih,
                                                 const float* __restrict__ Whh,
                                                 int first) {
    __shared__ float4 xs4[32][16];
    __shared__ float4 hs4[32][16];
    const float* __restrict__ h = first ? x0 : (const float*)g_node;

    int tid = threadIdx.x;
    int base = blockIdx.x * 32;

    for (int f4 = tid; f4 < 512; f4 += 192) {
        int nb = base + (f4 >> 4);
        int c = f4 & 15;
        float4 v = make_float4(0.f, 0.f, 0.f, 0.f), w = v;
        if (nb < NN) {
            v = *reinterpret_cast<const float4*>(&g_xin[nb * D + c * 4]);
            w = *reinterpret_cast<const float4*>(&h[nb * D + c * 4]);
        }
        xs4[f4 >> 4][c] = v;
        hs4[f4 >> 4][c] = w;
    }
    __syncthreads();

    int g = tid;  // 0..191
    int nmax = NN - base; if (nmax > 32) nmax = 32;

    float4 wr[16];
#pragma unroll
    for (int q = 0; q < 16; q++) wr[q] = reinterpret_cast<const float4*>(Wih)[g * 16 + q];
    for (int nn = 0; nn < nmax; nn++) {
        float acc = 0.f;
#pragma unroll
        for (int q = 0; q < 16; q++) {
            float4 xv = xs4[nn][q]; float4 wv = wr[q];
            acc = fmaf(xv.x, wv.x, acc); acc = fmaf(xv.y, wv.y, acc);
            acc = fmaf(xv.z, wv.z, acc); acc = fmaf(xv.w, wv.w, acc);
        }
        g_gi[(size_t)(base + nn) * 192 + g] = acc;
    }
#pragma unroll
    for (int q = 0; q < 16; q++) wr[q] = reinterpret_cast<const float4*>(Whh)[g * 16 + q];
    for (int nn = 0; nn < nmax; nn++) {
        float acc = 0.f;
#pragma unroll
        for (int q = 0; q < 16; q++) {
            float4 xv = hs4[nn][q]; float4 wv = wr[q];
            acc = fmaf(xv.x, wv.x, acc); acc = fmaf(xv.y, wv.y, acc);
            acc = fmaf(xv.z, wv.z, acc); acc = fmaf(xv.w, wv.w, acc);
        }
        g_gh[(size_t)(base + nn) * 192 + g] = acc;
    }
}

// ---------------- GRU gates + output accumulation ----------------
__global__ void k_gates(const float* __restrict__ x0,
                        const float* __restrict__ b_ih,
                        const float* __restrict__ b_hh,
                        int first) {
    int i = blockIdx.x * 256 + threadIdx.x;
    if (i >= NN * D) return;
    int n = i >> 6, j = i & 63;
    size_t o = (size_t)n * 192 + j;

    float ir = g_gi[o]       + b_ih[j];
    float iz = g_gi[o + 64]  + b_ih[64 + j];
    float in = g_gi[o + 128] + b_ih[128 + j];
    float hr = g_gh[o]       + b_hh[j];
    float hz = g_gh[o + 64]  + b_hh[64 + j];
    float hn = g_gh[o + 128] + b_hh[128 + j];

    float r = 1.0f / (1.0f + expf(-(ir + hr)));
    float z = 1.0f / (1.0f + expf(-(iz + hz)));
    float nv = tanhf(fmaf(r, hn, in));

    float hold = first ? x0[i] : g_node[i];
    float hnew = fmaf(z, hold - nv, nv);   // (1-z)*n + z*h

    if (first) g_acc[i] = hold;
    else       g_acc[i] += hold;
    g_node[i] = hnew;
}

// ---------------- out = (node0+node1+node2+node3)/4 + x0 ----------------
__global__ void k_final(const float* __restrict__ x0, float* __restrict__ out) {
    int i = blockIdx.x * 256 + threadIdx.x;
    if (i < NN * D) out[i] = (g_acc[i] + g_node[i]) * 0.25f + x0[i];
}

// ---------------- launcher ----------------
extern "C" void kernel_launch(void* const* d_in, const int* in_sizes, int n_in,
                              void* d_out, int out_size) {
    const float* node   = (const float*)d_in[0];
    const int*   ei     = (const int*)d_in[1];     // int32 (JAX x64 disabled)
    const float* edge   = (const float*)d_in[2];
    const float* W_edge = (const float*)d_in[3];
    const float* gamma  = (const float*)d_in[4];
    const float* beta   = (const float*)d_in[5];
    const float* bias   = (const float*)d_in[6];
    const float* W_ih   = (const float*)d_in[7];
    const float* W_hh   = (const float*)d_in[8];
    const float* b_ih   = (const float*)d_in[9];
    const float* b_hh   = (const float*)d_in[10];
    float* out = (float*)d_out;

    k_zero_pre<<<196, 256>>>();
    k_count<<<(NE + 255) / 256, 256>>>(ei);
    k_inv<<<196, 256>>>();

    dim3 gg(DD / 128, (NE + 127) / 128);
    k_gemm_edge<<<gg, 256>>>(edge, W_edge);
    k_bncoef<<<16, 256>>>(gamma, beta);

    // only 3 propagation steps needed: out = x0 + mean(node_0..node_3);
    // the reference's 4th GRU update is dead code.
    int nelem_blocks = (NN * D + 255) / 256;
    for (int s = 0; s < 3; s++) {
        int first = (s == 0) ? 1 : 0;
        k_zero_agg<<<nelem_blocks, 256>>>();
        k_msg<<<(NE + 31) / 32, 256>>>(node, ei, first);
        k_xin<<<nelem_blocks, 256>>>(bias);
        k_grugemm<<<(NN + 31) / 32, 192>>>(node, W_ih, W_hh, first);
        k_gates<<<nelem_blocks, 256>>>(node, b_ih, b_hh, first);
    }
    k_final<<<nelem_blocks, 256>>>(node, out);
}

// round 7
// speedup vs baseline: 1.9786x; 1.1924x over previous
#include <cuda_runtime.h>
#include <cuda_fp16.h>
#include <math.h>
#include <stdint.h>

#define NN 50000
#define NE 100000
#define D  64
#define F  128
#define DD 4096
#define EPSV 1e-5f
#define ECHUNK 25600   // multiple of 128 (GEMM tile rows); 4 chunks cover 102400 >= NE
#define NEPAD 100096   // NE rounded up to 128

// ---------------- scratch (static device globals; no runtime alloc) ----------------
// edge @ W_edge stored as fp16, split into 4 symbols of ~210 MB each
__device__ __align__(16) __half g_raw0[(size_t)ECHUNK * DD];
__device__ __align__(16) __half g_raw1[(size_t)ECHUNK * DD];
__device__ __align__(16) __half g_raw2[(size_t)ECHUNK * DD];
__device__ __align__(16) __half g_raw3[(size_t)ECHUNK * DD];

__device__ __forceinline__ __half* raw_row(int e) {
    int c = e / ECHUNK;
    int r = e - c * ECHUNK;
    __half* base = (c == 0) ? g_raw0 : (c == 1) ? g_raw1 : (c == 2) ? g_raw2 : g_raw3;
    return base + (size_t)r * DD;
}

// fp16 pre-converted GEMM operands
__device__ __align__(16) __half g_Ah[(size_t)NEPAD * F];   // 25.6 MB
__device__ __align__(16) __half g_Bh[(size_t)F * DD];      // 1 MB

__device__ __align__(16) float g_colsum[DD];
__device__ __align__(16) float g_colsq[DD];
__device__ __align__(16) float g_a[DD];
__device__ __align__(16) float g_c[DD];
__device__ __align__(16) float g_cnt[NN];
__device__ __align__(16) float g_inv[NN];
__device__ __align__(16) float g_agg[NN * D];
__device__ __align__(16) float g_xin[NN * D];
__device__ __align__(16) float g_node[NN * D];
__device__ __align__(16) float g_acc[NN * D];
__device__ __align__(16) float g_gi[(size_t)NN * 3 * D];
__device__ __align__(16) float g_gh[(size_t)NN * 3 * D];

struct alignas(8) H4 { __half2 x, y; };

// ---------------- zero / count helpers ----------------
__global__ void k_zero_pre() {
    int i = blockIdx.x * 256 + threadIdx.x;
    if (i < DD) { g_colsum[i] = 0.f; g_colsq[i] = 0.f; }
    if (i < NN) g_cnt[i] = 0.f;
}

__global__ void k_zero_agg() {
    int i = blockIdx.x * 256 + threadIdx.x;
    if (i < NN * D) g_agg[i] = 0.f;
}

__global__ void k_count(const int* __restrict__ ei) {
    int e = blockIdx.x * 256 + threadIdx.x;
    if (e < NE) atomicAdd(&g_cnt[ei[NE + e]], 1.0f);
}

__global__ void k_inv() {
    int i = blockIdx.x * 256 + threadIdx.x;
    if (i < NN) g_inv[i] = 1.0f / fmaxf(g_cnt[i], 1.0f);
}

// ---------------- fp32 -> fp16 pre-conversion ----------------
__global__ void k_toh_A(const float* __restrict__ A) {
    int i = blockIdx.x * 256 + threadIdx.x;   // one per 8 elems
    if (i >= NEPAD * F / 8) return;
    int r = i / (F / 8);
    H4 h0, h1;
    if (r < NE) {
        const float4* s = reinterpret_cast<const float4*>(A) + (size_t)i * 2;
        float4 v0 = s[0], v1 = s[1];
        h0.x = __floats2half2_rn(v0.x, v0.y); h0.y = __floats2half2_rn(v0.z, v0.w);
        h1.x = __floats2half2_rn(v1.x, v1.y); h1.y = __floats2half2_rn(v1.z, v1.w);
    } else {
        h0.x = h0.y = h1.x = h1.y = __floats2half2_rn(0.f, 0.f);
    }
    H4* d = reinterpret_cast<H4*>(g_Ah) + (size_t)i * 2;
    d[0] = h0; d[1] = h1;
}

__global__ void k_toh_B(const float* __restrict__ B) {
    int i = blockIdx.x * 256 + threadIdx.x;
    if (i >= F * DD / 8) return;
    const float4* s = reinterpret_cast<const float4*>(B) + (size_t)i * 2;
    float4 v0 = s[0], v1 = s[1];
    H4 h0, h1;
    h0.x = __floats2half2_rn(v0.x, v0.y); h0.y = __floats2half2_rn(v0.z, v0.w);
    h1.x = __floats2half2_rn(v1.x, v1.y); h1.y = __floats2half2_rn(v1.z, v1.w);
    H4* d = reinterpret_cast<H4*>(g_Bh) + (size_t)i * 2;
    d[0] = h0; d[1] = h1;
}

// ---------------- tensor-core GEMM helpers ----------------
__device__ __forceinline__ void ldsm_x4(uint32_t& r0, uint32_t& r1, uint32_t& r2, uint32_t& r3,
                                        uint32_t addr) {
    asm volatile("ldmatrix.sync.aligned.m8n8.x4.shared.b16 {%0,%1,%2,%3}, [%4];"
                 : "=r"(r0), "=r"(r1), "=r"(r2), "=r"(r3) : "r"(addr));
}
__device__ __forceinline__ void ldsm_x4_t(uint32_t& r0, uint32_t& r1, uint32_t& r2, uint32_t& r3,
                                          uint32_t addr) {
    asm volatile("ldmatrix.sync.aligned.m8n8.x4.trans.shared.b16 {%0,%1,%2,%3}, [%4];"
                 : "=r"(r0), "=r"(r1), "=r"(r2), "=r"(r3) : "r"(addr));
}
__device__ __forceinline__ void mma16816(float* c, const uint32_t* a, const uint32_t* b) {
    asm volatile(
        "mma.sync.aligned.m16n8k16.row.col.f32.f16.f16.f32 "
        "{%0,%1,%2,%3}, {%4,%5,%6,%7}, {%8,%9}, {%0,%1,%2,%3};"
        : "+f"(c[0]), "+f"(c[1]), "+f"(c[2]), "+f"(c[3])
        : "r"(a[0]), "r"(a[1]), "r"(a[2]), "r"(a[3]), "r"(b[0]), "r"(b[1]));
}
__device__ __forceinline__ void cpasync16(uint32_t smem, const void* gptr) {
    asm volatile("cp.async.cg.shared.global [%0], [%1], 16;" :: "r"(smem), "l"(gptr));
}

// ---------------- big GEMM: raw = A_h[NE,128] @ B_h[128,4096] + col stats ----
// HMMA m16n8k16, block tile 128x256, whole K=128 in SMEM via cp.async.
// 8 warps (2m x 4n), warp tile 64x64. fp32 accum; fp16 store staged via SMEM.
#define AS_STRIDE 136   // halves (272B = 17x16B: 16B-aligned, 4-bank row rotation)
#define BS_STRIDE 264   // halves (528B = 33x16B)
#define CS_STRIDE 264
#define GEMM_SMEM (128 * AS_STRIDE * 2 + 128 * BS_STRIDE * 2 + 2048 + 512)
__global__ __launch_bounds__(256) void k_gemm_edge() {
    extern __shared__ __align__(16) unsigned char sm[];
    __half* As = (__half*)sm;                                  // [128][136]
    __half* Bs = (__half*)(sm + 128 * AS_STRIDE * 2);          // [128][264]
    __half* Cs = (__half*)sm;                                  // [128][264] (reuse)
    float* csum = (float*)(sm + 128 * AS_STRIDE * 2 + 128 * BS_STRIDE * 2);  // [256]
    float* csq  = csum + 256;

    int tid = threadIdx.x;
    int warp = tid >> 5, lane = tid & 31;
    int wm = warp & 1, wn = warp >> 1;      // 2 (m) x 4 (n, 64-wide)
    int gid = lane >> 2, tig = lane & 3;
    int m0 = blockIdx.y * 128, n0 = blockIdx.x * 256;

    // ---- async load whole-K tiles ----
    {
        uint32_t as_b = (uint32_t)__cvta_generic_to_shared(As);
#pragma unroll
        for (int it = 0; it < 8; it++) {           // A: 128x128 halves = 2048 x 16B
            int idx = it * 256 + tid;
            int r = idx >> 4, c16 = idx & 15;
            cpasync16(as_b + (r * AS_STRIDE + c16 * 8) * 2,
                      g_Ah + (size_t)(m0 + r) * F + c16 * 8);
        }
        uint32_t bs_b = (uint32_t)__cvta_generic_to_shared(Bs);
#pragma unroll
        for (int it = 0; it < 16; it++) {          // B: 128x256 halves = 4096 x 16B
            int idx = it * 256 + tid;
            int r = idx >> 5, c16 = idx & 31;
            cpasync16(bs_b + (r * BS_STRIDE + c16 * 8) * 2,
                      g_Bh + (size_t)r * DD + n0 + c16 * 8);
        }
        asm volatile("cp.async.commit_group;");
    }
    if (tid < 256) { csum[tid] = 0.f; csq[tid] = 0.f; }
    asm volatile("cp.async.wait_group 0;");
    __syncthreads();

    float c[4][8][4];
#pragma unroll
    for (int i = 0; i < 4; i++)
#pragma unroll
        for (int j = 0; j < 8; j++)
#pragma unroll
            for (int q = 0; q < 4; q++) c[i][j][q] = 0.f;

#pragma unroll
    for (int ks = 0; ks < 8; ks++) {
        uint32_t a[4][4], b[8][2];
#pragma unroll
        for (int mi = 0; mi < 4; mi++) {
            int row = wm * 64 + mi * 16 + (lane & 15);
            int kof = ks * 16 + ((lane >> 4) << 3);
            uint32_t addr = (uint32_t)__cvta_generic_to_shared(&As[row * AS_STRIDE + kof]);
            ldsm_x4(a[mi][0], a[mi][1], a[mi][2], a[mi][3], addr);
        }
#pragma unroll
        for (int hb = 0; hb < 4; hb++) {
            int krow = ks * 16 + (lane & 15);
            int ncol = wn * 64 + hb * 16 + ((lane >> 4) << 3);
            uint32_t addr = (uint32_t)__cvta_generic_to_shared(&Bs[krow * BS_STRIDE + ncol]);
            ldsm_x4_t(b[2 * hb][0], b[2 * hb][1], b[2 * hb + 1][0], b[2 * hb + 1][1], addr);
        }
#pragma unroll
        for (int mi = 0; mi < 4; mi++)
#pragma unroll
            for (int ni = 0; ni < 8; ni++)
                mma16816(c[mi][ni], a[mi], b[ni]);
    }
    __syncthreads();   // all warps done reading As/Bs before C overwrite

    // ---- epilogue: stats (fp32 accumulators) + staged fp16 store ----
    float psum[16], psq[16];
#pragma unroll
    for (int j = 0; j < 16; j++) { psum[j] = 0.f; psq[j] = 0.f; }
#pragma unroll
    for (int mi = 0; mi < 4; mi++) {
#pragma unroll
        for (int ni = 0; ni < 8; ni++) {
            int row0 = wm * 64 + mi * 16 + gid;
            int col = wn * 64 + ni * 8 + tig * 2;
            *reinterpret_cast<__half2*>(&Cs[row0 * CS_STRIDE + col]) =
                __floats2half2_rn(c[mi][ni][0], c[mi][ni][1]);
            *reinterpret_cast<__half2*>(&Cs[(row0 + 8) * CS_STRIDE + col]) =
                __floats2half2_rn(c[mi][ni][2], c[mi][ni][3]);
            psum[ni * 2]     += c[mi][ni][0] + c[mi][ni][2];
            psum[ni * 2 + 1] += c[mi][ni][1] + c[mi][ni][3];
            psq[ni * 2]      += c[mi][ni][0] * c[mi][ni][0] + c[mi][ni][2] * c[mi][ni][2];
            psq[ni * 2 + 1]  += c[mi][ni][1] * c[mi][ni][1] + c[mi][ni][3] * c[mi][ni][3];
        }
    }
#pragma unroll
    for (int ni = 0; ni < 8; ni++) {
#pragma unroll
        for (int t = 0; t < 2; t++) {
            int col = wn * 64 + ni * 8 + tig * 2 + t;
            atomicAdd(&csum[col], psum[ni * 2 + t]);
            atomicAdd(&csq[col],  psq[ni * 2 + t]);
        }
    }
    __syncthreads();

    // coalesced fp16 store: 2 threads per row, 128 halves (256B) each
    {
        int r = tid >> 1, seg = tid & 1;
        if (m0 + r < NE) {
            __half* dst = raw_row(m0 + r) + n0 + seg * 128;
            const __half* src = &Cs[r * CS_STRIDE + seg * 128];
#pragma unroll
            for (int q = 0; q < 16; q++)
                *reinterpret_cast<uint4*>(&dst[q * 8]) =
                    *reinterpret_cast<const uint4*>(&src[q * 8]);
        }
    }
    if (tid < 256) {
        atomicAdd(&g_colsum[n0 + tid], csum[tid]);
        atomicAdd(&g_colsq[n0 + tid],  csq[tid]);
    }
}

// ---------------- BN coefficients ----------------
__global__ void k_bncoef(const float* __restrict__ gamma, const float* __restrict__ beta) {
    int i = blockIdx.x * 256 + threadIdx.x;
    if (i < DD) {
        float mu  = g_colsum[i] * (1.0f / NE);
        float var = g_colsq[i] * (1.0f / NE) - mu * mu;
        float a = gamma[i] * rsqrtf(var + EPSV);
        g_a[i] = a;
        g_c[i] = beta[i] - mu * a;
    }
}

// ---------------- message + scatter: agg[dst] += x[src] . (a*raw + c) -------------
__global__ __launch_bounds__(256) void k_msg(const float* __restrict__ x0,
                                             const int* __restrict__ ei,
                                             int first) {
    __shared__ __align__(16) float a_s[DD];
    __shared__ __align__(16) float c_s[DD];
    __shared__ float xs[4][D];

    const float* __restrict__ x = first ? x0 : (const float*)g_node;
    int tid = threadIdx.x;
    for (int i = tid * 4; i < DD; i += 1024) {
        *reinterpret_cast<float4*>(&a_s[i]) = *reinterpret_cast<const float4*>(&g_a[i]);
        *reinterpret_cast<float4*>(&c_s[i]) = *reinterpret_cast<const float4*>(&g_c[i]);
    }
    __syncthreads();

    int sub = tid >> 6, k = tid & 63;
    int ebase = blockIdx.x * 32;

    for (int it = 0; it < 8; it++) {
        int e = ebase + it * 4 + sub;
        bool valid = e < NE;
        int dst = 0;
        if (valid) {
            int src = ei[e];
            dst = ei[NE + e];
            xs[sub][k] = x[src * D + k];
        }
        __syncthreads();
        if (valid) {
            const __half* rp = raw_row(e) + k;
            float acc0 = 0.f, acc1 = 0.f;
#pragma unroll
            for (int d = 0; d < D; d += 2) {
                int i0 = d * 64 + k;
                float r0 = __half2float(rp[d * 64]);
                float r1 = __half2float(rp[(d + 1) * 64]);
                acc0 = fmaf(xs[sub][d],     fmaf(a_s[i0],      r0, c_s[i0]),      acc0);
                acc1 = fmaf(xs[sub][d + 1], fmaf(a_s[i0 + 64], r1, c_s[i0 + 64]), acc1);
            }
            atomicAdd(&g_agg[dst * D + k], acc0 + acc1);
        }
        __syncthreads();
    }
}

// ---------------- node_in = relu(agg/cnt + bias) ----------------
__global__ void k_xin(const float* __restrict__ bias) {
    int i = blockIdx.x * 256 + threadIdx.x;
    if (i < NN * D) {
        float v = fmaf(g_agg[i], g_inv[i >> 6], bias[i & 63]);
        g_xin[i] = fmaxf(v, 0.f);
    }
}

// ---------------- GRU GEMVs: gi = xin@W_ih^T, gh = h@W_hh^T ----------------
__global__ __launch_bounds__(192) void k_grugemm(const float* __restrict__ x0,
                                                 const float* __restrict__ Wih,
                                                 const float* __restrict__ Whh,
                                                 int first) {
    __shared__ float4 xs4[32][16];
    __shared__ float4 hs4[32][16];
    const float* __restrict__ h = first ? x0 : (const float*)g_node;

    int tid = threadIdx.x;
    int base = blockIdx.x * 32;

    for (int f4 = tid; f4 < 512; f4 += 192) {
        int nb = base + (f4 >> 4);
        int c = f4 & 15;
        float4 v = make_float4(0.f, 0.f, 0.f, 0.f), w = v;
        if (nb < NN) {
            v = *reinterpret_cast<const float4*>(&g_xin[nb * D + c * 4]);
            w = *reinterpret_cast<const float4*>(&h[nb * D + c * 4]);
        }
        xs4[f4 >> 4][c] = v;
        hs4[f4 >> 4][c] = w;
    }
    __syncthreads();

    int g = tid;  // 0..191
    int nmax = NN - base; if (nmax > 32) nmax = 32;

    float4 wr[16];
#pragma unroll
    for (int q = 0; q < 16; q++) wr[q] = reinterpret_cast<const float4*>(Wih)[g * 16 + q];
    for (int nn = 0; nn < nmax; nn++) {
        float acc = 0.f;
#pragma unroll
        for (int q = 0; q < 16; q++) {
            float4 xv = xs4[nn][q]; float4 wv = wr[q];
            acc = fmaf(xv.x, wv.x, acc); acc = fmaf(xv.y, wv.y, acc);
            acc = fmaf(xv.z, wv.z, acc); acc = fmaf(xv.w, wv.w, acc);
        }
        g_gi[(size_t)(base + nn) * 192 + g] = acc;
    }
#pragma unroll
    for (int q = 0; q < 16; q++) wr[q] = reinterpret_cast<const float4*>(Whh)[g * 16 + q];
    for (int nn = 0; nn < nmax; nn++) {
        float acc = 0.f;
#pragma unroll
        for (int q = 0; q < 16; q++) {
            float4 xv = hs4[nn][q]; float4 wv = wr[q];
            acc = fmaf(xv.x, wv.x, acc); acc = fmaf(xv.y, wv.y, acc);
            acc = fmaf(xv.z, wv.z, acc); acc = fmaf(xv.w, wv.w, acc);
        }
        g_gh[(size_t)(base + nn) * 192 + g] = acc;
    }
}

// ---------------- GRU gates + output accumulation ----------------
__global__ void k_gates(const float* __restrict__ x0,
                        const float* __restrict__ b_ih,
                        const float* __restrict__ b_hh,
                        int first) {
    int i = blockIdx.x * 256 + threadIdx.x;
    if (i >= NN * D) return;
    int n = i >> 6, j = i & 63;
    size_t o = (size_t)n * 192 + j;

    float ir = g_gi[o]       + b_ih[j];
    float iz = g_gi[o + 64]  + b_ih[64 + j];
    float in = g_gi[o + 128] + b_ih[128 + j];
    float hr = g_gh[o]       + b_hh[j];
    float hz = g_gh[o + 64]  + b_hh[64 + j];
    float hn = g_gh[o + 128] + b_hh[128 + j];

    float r = 1.0f / (1.0f + expf(-(ir + hr)));
    float z = 1.0f / (1.0f + expf(-(iz + hz)));
    float nv = tanhf(fmaf(r, hn, in));

    float hold = first ? x0[i] : g_node[i];
    float hnew = fmaf(z, hold - nv, nv);   // (1-z)*n + z*h

    if (first) g_acc[i] = hold;
    else       g_acc[i] += hold;
    g_node[i] = hnew;
}

// ---------------- out = (node0+node1+node2+node3)/4 + x0 ----------------
__global__ void k_final(const float* __restrict__ x0, float* __restrict__ out) {
    int i = blockIdx.x * 256 + threadIdx.x;
    if (i < NN * D) out[i] = (g_acc[i] + g_node[i]) * 0.25f + x0[i];
}

// ---------------- launcher ----------------
extern "C" void kernel_launch(void* const* d_in, const int* in_sizes, int n_in,
                              void* d_out, int out_size) {
    const float* node   = (const float*)d_in[0];
    const int*   ei     = (const int*)d_in[1];     // int32 (JAX x64 disabled)
    const float* edge   = (const float*)d_in[2];
    const float* W_edge = (const float*)d_in[3];
    const float* gamma  = (const float*)d_in[4];
    const float* beta   = (const float*)d_in[5];
    const float* bias   = (const float*)d_in[6];
    const float* W_ih   = (const float*)d_in[7];
    const float* W_hh   = (const float*)d_in[8];
    const float* b_ih   = (const float*)d_in[9];
    const float* b_hh   = (const float*)d_in[10];
    float* out = (float*)d_out;

    cudaFuncSetAttribute(k_gemm_edge, cudaFuncAttributeMaxDynamicSharedMemorySize, GEMM_SMEM);

    k_zero_pre<<<196, 256>>>();
    k_count<<<(NE + 255) / 256, 256>>>(ei);
    k_inv<<<196, 256>>>();

    k_toh_A<<<(NEPAD * F / 8 + 255) / 256, 256>>>(edge);
    k_toh_B<<<(F * DD / 8 + 255) / 256, 256>>>(W_edge);

    dim3 gg(DD / 256, NEPAD / 128);
    k_gemm_edge<<<gg, 256, GEMM_SMEM>>>();
    k_bncoef<<<16, 256>>>(gamma, beta);

    // only 3 propagation steps needed: out = x0 + mean(node_0..node_3);
    // the reference's 4th GRU update is dead code.
    int nelem_blocks = (NN * D + 255) / 256;
    for (int s = 0; s < 3; s++) {
        int first = (s == 0) ? 1 : 0;
        k_zero_agg<<<nelem_blocks, 256>>>();
        k_msg<<<(NE + 31) / 32, 256>>>(node, ei, first);
        k_xin<<<nelem_blocks, 256>>>(bias);
        k_grugemm<<<(NN + 31) / 32, 192>>>(node, W_ih, W_hh, first);
        k_gates<<<nelem_blocks, 256>>>(node, b_ih, b_hh, first);
    }
    k_final<<<nelem_blocks, 256>>>(node, out);
}

// round 8
// speedup vs baseline: 2.4391x; 1.2327x over previous
#include <cuda_runtime.h>
#include <cuda_fp16.h>
#include <math.h>
#include <stdint.h>

#define NN 50000
#define NE 100000
#define D  64
#define F  128
#define DD 4096
#define EPSV 1e-5f
#define ECHUNK 25600   // multiple of 128 (GEMM tile rows); 4 chunks cover 102400 >= NE
#define NEPAD 100096   // NE rounded up to 128

// ---------------- scratch (static device globals; no runtime alloc) ----------------
// edge @ W_edge stored as fp16, split into 4 symbols of ~210 MB each
__device__ __align__(16) __half g_raw0[(size_t)ECHUNK * DD];
__device__ __align__(16) __half g_raw1[(size_t)ECHUNK * DD];
__device__ __align__(16) __half g_raw2[(size_t)ECHUNK * DD];
__device__ __align__(16) __half g_raw3[(size_t)ECHUNK * DD];

__device__ __forceinline__ __half* raw_row(int e) {
    int c = e / ECHUNK;
    int r = e - c * ECHUNK;
    __half* base = (c == 0) ? g_raw0 : (c == 1) ? g_raw1 : (c == 2) ? g_raw2 : g_raw3;
    return base + (size_t)r * DD;
}

// fp16 pre-converted GEMM operands
__device__ __align__(16) __half g_Ah[(size_t)NEPAD * F];   // 25.6 MB
__device__ __align__(16) __half g_Bh[(size_t)F * DD];      // 1 MB

__device__ __align__(16) float g_colsum[DD];
__device__ __align__(16) float g_colsq[DD];
__device__ __align__(16) float g_a[DD];
__device__ __align__(16) float g_c[DD];
__device__ __align__(16) float g_cnt[NN];
__device__ __align__(16) float g_inv[NN];
__device__ __align__(16) float g_agg[NN * D];
__device__ __align__(16) float g_xin[NN * D];
__device__ __align__(16) float g_node[NN * D];
__device__ __align__(16) float g_acc[NN * D];
__device__ __align__(16) float g_gi[(size_t)NN * 3 * D];
__device__ __align__(16) float g_gh[(size_t)NN * 3 * D];

struct alignas(8) H4 { __half2 x, y; };

// ---------------- zero / count helpers ----------------
__global__ void k_zero_pre() {
    int i = blockIdx.x * 256 + threadIdx.x;
    if (i < DD) { g_colsum[i] = 0.f; g_colsq[i] = 0.f; }
    if (i < NN) g_cnt[i] = 0.f;
}

__global__ void k_zero_agg() {
    int i = blockIdx.x * 256 + threadIdx.x;
    if (i < NN * D) g_agg[i] = 0.f;
}

__global__ void k_count(const int* __restrict__ ei) {
    int e = blockIdx.x * 256 + threadIdx.x;
    if (e < NE) atomicAdd(&g_cnt[ei[NE + e]], 1.0f);
}

__global__ void k_inv() {
    int i = blockIdx.x * 256 + threadIdx.x;
    if (i < NN) g_inv[i] = 1.0f / fmaxf(g_cnt[i], 1.0f);
}

// ---------------- fp32 -> fp16 pre-conversion ----------------
__global__ void k_toh_A(const float* __restrict__ A) {
    int i = blockIdx.x * 256 + threadIdx.x;   // one per 8 elems
    if (i >= NEPAD * F / 8) return;
    int r = i / (F / 8);
    H4 h0, h1;
    if (r < NE) {
        const float4* s = reinterpret_cast<const float4*>(A) + (size_t)i * 2;
        float4 v0 = s[0], v1 = s[1];
        h0.x = __floats2half2_rn(v0.x, v0.y); h0.y = __floats2half2_rn(v0.z, v0.w);
        h1.x = __floats2half2_rn(v1.x, v1.y); h1.y = __floats2half2_rn(v1.z, v1.w);
    } else {
        h0.x = h0.y = h1.x = h1.y = __floats2half2_rn(0.f, 0.f);
    }
    H4* d = reinterpret_cast<H4*>(g_Ah) + (size_t)i * 2;
    d[0] = h0; d[1] = h1;
}

__global__ void k_toh_B(const float* __restrict__ B) {
    int i = blockIdx.x * 256 + threadIdx.x;
    if (i >= F * DD / 8) return;
    const float4* s = reinterpret_cast<const float4*>(B) + (size_t)i * 2;
    float4 v0 = s[0], v1 = s[1];
    H4 h0, h1;
    h0.x = __floats2half2_rn(v0.x, v0.y); h0.y = __floats2half2_rn(v0.z, v0.w);
    h1.x = __floats2half2_rn(v1.x, v1.y); h1.y = __floats2half2_rn(v1.z, v1.w);
    H4* d = reinterpret_cast<H4*>(g_Bh) + (size_t)i * 2;
    d[0] = h0; d[1] = h1;
}

// ---------------- tensor-core GEMM helpers ----------------
__device__ __forceinline__ void ldsm_x4(uint32_t& r0, uint32_t& r1, uint32_t& r2, uint32_t& r3,
                                        uint32_t addr) {
    asm volatile("ldmatrix.sync.aligned.m8n8.x4.shared.b16 {%0,%1,%2,%3}, [%4];"
                 : "=r"(r0), "=r"(r1), "=r"(r2), "=r"(r3) : "r"(addr));
}
__device__ __forceinline__ void ldsm_x4_t(uint32_t& r0, uint32_t& r1, uint32_t& r2, uint32_t& r3,
                                          uint32_t addr) {
    asm volatile("ldmatrix.sync.aligned.m8n8.x4.trans.shared.b16 {%0,%1,%2,%3}, [%4];"
                 : "=r"(r0), "=r"(r1), "=r"(r2), "=r"(r3) : "r"(addr));
}
__device__ __forceinline__ void mma16816(float* c, const uint32_t* a, const uint32_t* b) {
    asm volatile(
        "mma.sync.aligned.m16n8k16.row.col.f32.f16.f16.f32 "
        "{%0,%1,%2,%3}, {%4,%5,%6,%7}, {%8,%9}, {%0,%1,%2,%3};"
        : "+f"(c[0]), "+f"(c[1]), "+f"(c[2]), "+f"(c[3])
        : "r"(a[0]), "r"(a[1]), "r"(a[2]), "r"(a[3]), "r"(b[0]), "r"(b[1]));
}
__device__ __forceinline__ void cpasync16(uint32_t smem, const void* gptr) {
    asm volatile("cp.async.cg.shared.global [%0], [%1], 16;" :: "r"(smem), "l"(gptr));
}

// ---------------- big GEMM: raw = A_h[NE,128] @ B_h[128,4096] + col stats ----
// HMMA m16n8k16, block tile 128x128, whole K=128 in SMEM via cp.async.
// 8 warps (2m x 4n), warp tile 64x32. regs capped for 2 CTAs/SM (16 warps).
#define AS_STRIDE 136   // halves (272B = 17x16B: 16B-aligned, 4-bank row rotation)
#define BS_STRIDE 136
#define CS_STRIDE 136
#define GEMM_SMEM (128 * AS_STRIDE * 2 * 2 + 1024)
__global__ __launch_bounds__(256, 2) void k_gemm_edge() {
    extern __shared__ __align__(16) unsigned char sm[];
    __half* As = (__half*)sm;                                  // [128][136]
    __half* Bs = (__half*)(sm + 128 * AS_STRIDE * 2);          // [128][136]
    __half* Cs = (__half*)sm;                                  // [128][136] (reuse)
    float* csum = (float*)(sm + 128 * AS_STRIDE * 2 * 2);      // [128]
    float* csq  = csum + 128;

    int tid = threadIdx.x;
    int warp = tid >> 5, lane = tid & 31;
    int wm = warp & 1, wn = warp >> 1;      // 2 (m) x 4 (n, 32-wide)
    int gid = lane >> 2, tig = lane & 3;
    int m0 = blockIdx.y * 128, n0 = blockIdx.x * 128;

    // ---- async load whole-K tiles (A: 128x128 halves, B: 128x128 halves) ----
    {
        uint32_t as_b = (uint32_t)__cvta_generic_to_shared(As);
#pragma unroll
        for (int it = 0; it < 8; it++) {
            int idx = it * 256 + tid;
            int r = idx >> 4, c16 = idx & 15;
            cpasync16(as_b + (r * AS_STRIDE + c16 * 8) * 2,
                      g_Ah + (size_t)(m0 + r) * F + c16 * 8);
        }
        uint32_t bs_b = (uint32_t)__cvta_generic_to_shared(Bs);
#pragma unroll
        for (int it = 0; it < 8; it++) {
            int idx = it * 256 + tid;
            int r = idx >> 4, c16 = idx & 15;
            cpasync16(bs_b + (r * BS_STRIDE + c16 * 8) * 2,
                      g_Bh + (size_t)r * DD + n0 + c16 * 8);
        }
        asm volatile("cp.async.commit_group;");
    }
    if (tid < 128) { csum[tid] = 0.f; csq[tid] = 0.f; }
    asm volatile("cp.async.wait_group 0;");
    __syncthreads();

    float c[4][4][4];
#pragma unroll
    for (int i = 0; i < 4; i++)
#pragma unroll
        for (int j = 0; j < 4; j++)
#pragma unroll
            for (int q = 0; q < 4; q++) c[i][j][q] = 0.f;

#pragma unroll
    for (int ks = 0; ks < 8; ks++) {
        uint32_t a[4][4], b[4][2];
#pragma unroll
        for (int mi = 0; mi < 4; mi++) {
            int row = wm * 64 + mi * 16 + (lane & 15);
            int kof = ks * 16 + ((lane >> 4) << 3);
            uint32_t addr = (uint32_t)__cvta_generic_to_shared(&As[row * AS_STRIDE + kof]);
            ldsm_x4(a[mi][0], a[mi][1], a[mi][2], a[mi][3], addr);
        }
#pragma unroll
        for (int hb = 0; hb < 2; hb++) {
            int krow = ks * 16 + (lane & 15);
            int ncol = wn * 32 + hb * 16 + ((lane >> 4) << 3);
            uint32_t addr = (uint32_t)__cvta_generic_to_shared(&Bs[krow * BS_STRIDE + ncol]);
            ldsm_x4_t(b[2 * hb][0], b[2 * hb][1], b[2 * hb + 1][0], b[2 * hb + 1][1], addr);
        }
#pragma unroll
        for (int mi = 0; mi < 4; mi++)
#pragma unroll
            for (int ni = 0; ni < 4; ni++)
                mma16816(c[mi][ni], a[mi], b[ni]);
    }
    __syncthreads();   // all warps done reading As/Bs before C overwrite

    // ---- epilogue: stats (fp32 accumulators) + staged fp16 store ----
    float psum[8], psq[8];
#pragma unroll
    for (int j = 0; j < 8; j++) { psum[j] = 0.f; psq[j] = 0.f; }
#pragma unroll
    for (int mi = 0; mi < 4; mi++) {
#pragma unroll
        for (int ni = 0; ni < 4; ni++) {
            int row0 = wm * 64 + mi * 16 + gid;
            int col = wn * 32 + ni * 8 + tig * 2;
            *reinterpret_cast<__half2*>(&Cs[row0 * CS_STRIDE + col]) =
                __floats2half2_rn(c[mi][ni][0], c[mi][ni][1]);
            *reinterpret_cast<__half2*>(&Cs[(row0 + 8) * CS_STRIDE + col]) =
                __floats2half2_rn(c[mi][ni][2], c[mi][ni][3]);
            psum[ni * 2]     += c[mi][ni][0] + c[mi][ni][2];
            psum[ni * 2 + 1] += c[mi][ni][1] + c[mi][ni][3];
            psq[ni * 2]      += c[mi][ni][0] * c[mi][ni][0] + c[mi][ni][2] * c[mi][ni][2];
            psq[ni * 2 + 1]  += c[mi][ni][1] * c[mi][ni][1] + c[mi][ni][3] * c[mi][ni][3];
        }
    }
#pragma unroll
    for (int ni = 0; ni < 4; ni++) {
#pragma unroll
        for (int t = 0; t < 2; t++) {
            int col = wn * 32 + ni * 8 + tig * 2 + t;
            atomicAdd(&csum[col], psum[ni * 2 + t]);
            atomicAdd(&csq[col],  psq[ni * 2 + t]);
        }
    }
    __syncthreads();

    // coalesced fp16 store: 2 threads per row, 64 halves (128B) each
    {
        int r = tid >> 1, seg = tid & 1;
        if (m0 + r < NE) {
            __half* dst = raw_row(m0 + r) + n0 + seg * 64;
            const __half* src = &Cs[r * CS_STRIDE + seg * 64];
#pragma unroll
            for (int q = 0; q < 8; q++)
                *reinterpret_cast<uint4*>(&dst[q * 8]) =
                    *reinterpret_cast<const uint4*>(&src[q * 8]);
        }
    }
    if (tid < 128) {
        atomicAdd(&g_colsum[n0 + tid], csum[tid]);
        atomicAdd(&g_colsq[n0 + tid],  csq[tid]);
    }
}

// ---------------- BN coefficients ----------------
__global__ void k_bncoef(const float* __restrict__ gamma, const float* __restrict__ beta) {
    int i = blockIdx.x * 256 + threadIdx.x;
    if (i < DD) {
        float mu  = g_colsum[i] * (1.0f / NE);
        float var = g_colsq[i] * (1.0f / NE) - mu * mu;
        float a = gamma[i] * rsqrtf(var + EPSV);
        g_a[i] = a;
        g_c[i] = beta[i] - mu * a;
    }
}

// ---------------- message + scatter: agg[dst] += x[src] . (a*raw + c) -------------
__global__ __launch_bounds__(256) void k_msg(const float* __restrict__ x0,
                                             const int* __restrict__ ei,
                                             int first) {
    __shared__ __align__(16) float a_s[DD];
    __shared__ __align__(16) float c_s[DD];
    __shared__ float xs[4][D];

    const float* __restrict__ x = first ? x0 : (const float*)g_node;
    int tid = threadIdx.x;
    for (int i = tid * 4; i < DD; i += 1024) {
        *reinterpret_cast<float4*>(&a_s[i]) = *reinterpret_cast<const float4*>(&g_a[i]);
        *reinterpret_cast<float4*>(&c_s[i]) = *reinterpret_cast<const float4*>(&g_c[i]);
    }
    __syncthreads();

    int sub = tid >> 6, k = tid & 63;
    int ebase = blockIdx.x * 32;

    for (int it = 0; it < 8; it++) {
        int e = ebase + it * 4 + sub;
        bool valid = e < NE;
        int dst = 0;
        if (valid) {
            int src = ei[e];
            dst = ei[NE + e];
            xs[sub][k] = x[src * D + k];
        }
        __syncthreads();
        if (valid) {
            const __half* rp = raw_row(e) + k;
            float acc0 = 0.f, acc1 = 0.f;
#pragma unroll
            for (int d = 0; d < D; d += 2) {
                int i0 = d * 64 + k;
                float r0 = __half2float(rp[d * 64]);
                float r1 = __half2float(rp[(d + 1) * 64]);
                acc0 = fmaf(xs[sub][d],     fmaf(a_s[i0],      r0, c_s[i0]),      acc0);
                acc1 = fmaf(xs[sub][d + 1], fmaf(a_s[i0 + 64], r1, c_s[i0 + 64]), acc1);
            }
            atomicAdd(&g_agg[dst * D + k], acc0 + acc1);
        }
        __syncthreads();
    }
}

// ---------------- node_in = relu(agg/cnt + bias) ----------------
__global__ void k_xin(const float* __restrict__ bias) {
    int i = blockIdx.x * 256 + threadIdx.x;
    if (i < NN * D) {
        float v = fmaf(g_agg[i], g_inv[i >> 6], bias[i & 63]);
        g_xin[i] = fmaxf(v, 0.f);
    }
}

// ---------------- GRU GEMVs: gi = xin@W_ih^T, gh = h@W_hh^T ----------------
__global__ __launch_bounds__(192) void k_grugemm(const float* __restrict__ x0,
                                                 const float* __restrict__ Wih,
                                                 const float* __restrict__ Whh,
                                                 int first) {
    __shared__ float4 xs4[32][16];
    __shared__ float4 hs4[32][16];
    const float* __restrict__ h = first ? x0 : (const float*)g_node;

    int tid = threadIdx.x;
    int base = blockIdx.x * 32;

    for (int f4 = tid; f4 < 512; f4 += 192) {
        int nb = base + (f4 >> 4);
        int c = f4 & 15;
        float4 v = make_float4(0.f, 0.f, 0.f, 0.f), w = v;
        if (nb < NN) {
            v = *reinterpret_cast<const float4*>(&g_xin[nb * D + c * 4]);
            w = *reinterpret_cast<const float4*>(&h[nb * D + c * 4]);
        }
        xs4[f4 >> 4][c] = v;
        hs4[f4 >> 4][c] = w;
    }
    __syncthreads();

    int g = tid;  // 0..191
    int nmax = NN - base; if (nmax > 32) nmax = 32;

    float4 wr[16];
#pragma unroll
    for (int q = 0; q < 16; q++) wr[q] = reinterpret_cast<const float4*>(Wih)[g * 16 + q];
    for (int nn = 0; nn < nmax; nn++) {
        float acc = 0.f;
#pragma unroll
        for (int q = 0; q < 16; q++) {
            float4 xv = xs4[nn][q]; float4 wv = wr[q];
            acc = fmaf(xv.x, wv.x, acc); acc = fmaf(xv.y, wv.y, acc);
            acc = fmaf(xv.z, wv.z, acc); acc = fmaf(xv.w, wv.w, acc);
        }
        g_gi[(size_t)(base + nn) * 192 + g] = acc;
    }
#pragma unroll
    for (int q = 0; q < 16; q++) wr[q] = reinterpret_cast<const float4*>(Whh)[g * 16 + q];
    for (int nn = 0; nn < nmax; nn++) {
        float acc = 0.f;
#pragma unroll
        for (int q = 0; q < 16; q++) {
            float4 xv = hs4[nn][q]; float4 wv = wr[q];
            acc = fmaf(xv.x, wv.x, acc); acc = fmaf(xv.y, wv.y, acc);
            acc = fmaf(xv.z, wv.z, acc); acc = fmaf(xv.w, wv.w, acc);
        }
        g_gh[(size_t)(base + nn) * 192 + g] = acc;
    }
}

// ---------------- GRU gates + output accumulation ----------------
__global__ void k_gates(const float* __restrict__ x0,
                        const float* __restrict__ b_ih,
                        const float* __restrict__ b_hh,
                        int first) {
    int i = blockIdx.x * 256 + threadIdx.x;
    if (i >= NN * D) return;
    int n = i >> 6, j = i & 63;
    size_t o = (size_t)n * 192 + j;

    float ir = g_gi[o]       + b_ih[j];
    float iz = g_gi[o + 64]  + b_ih[64 + j];
    float in = g_gi[o + 128] + b_ih[128 + j];
    float hr = g_gh[o]       + b_hh[j];
    float hz = g_gh[o + 64]  + b_hh[64 + j];
    float hn = g_gh[o + 128] + b_hh[128 + j];

    float r = 1.0f / (1.0f + expf(-(ir + hr)));
    float z = 1.0f / (1.0f + expf(-(iz + hz)));
    float nv = tanhf(fmaf(r, hn, in));

    float hold = first ? x0[i] : g_node[i];
    float hnew = fmaf(z, hold - nv, nv);   // (1-z)*n + z*h

    if (first) g_acc[i] = hold;
    else       g_acc[i] += hold;
    g_node[i] = hnew;
}

// ---------------- out = (node0+node1+node2+node3)/4 + x0 ----------------
__global__ void k_final(const float* __restrict__ x0, float* __restrict__ out) {
    int i = blockIdx.x * 256 + threadIdx.x;
    if (i < NN * D) out[i] = (g_acc[i] + g_node[i]) * 0.25f + x0[i];
}

// ---------------- launcher ----------------
extern "C" void kernel_launch(void* const* d_in, const int* in_sizes, int n_in,
                              void* d_out, int out_size) {
    const float* node   = (const float*)d_in[0];
    const int*   ei     = (const int*)d_in[1];     // int32 (JAX x64 disabled)
    const float* edge   = (const float*)d_in[2];
    const float* W_edge = (const float*)d_in[3];
    const float* gamma  = (const float*)d_in[4];
    const float* beta   = (const float*)d_in[5];
    const float* bias   = (const float*)d_in[6];
    const float* W_ih   = (const float*)d_in[7];
    const float* W_hh   = (const float*)d_in[8];
    const float* b_ih   = (const float*)d_in[9];
    const float* b_hh   = (const float*)d_in[10];
    float* out = (float*)d_out;

    cudaFuncSetAttribute(k_gemm_edge, cudaFuncAttributeMaxDynamicSharedMemorySize, GEMM_SMEM);

    k_zero_pre<<<196, 256>>>();
    k_count<<<(NE + 255) / 256, 256>>>(ei);
    k_inv<<<196, 256>>>();

    k_toh_A<<<(NEPAD * F / 8 + 255) / 256, 256>>>(edge);
    k_toh_B<<<(F * DD / 8 + 255) / 256, 256>>>(W_edge);

    dim3 gg(DD / 128, NEPAD / 128);
    k_gemm_edge<<<gg, 256, GEMM_SMEM>>>();
    k_bncoef<<<16, 256>>>(gamma, beta);

    // only 3 propagation steps needed: out = x0 + mean(node_0..node_3);
    // the reference's 4th GRU update is dead code.
    int nelem_blocks = (NN * D + 255) / 256;
    for (int s = 0; s < 3; s++) {
        int first = (s == 0) ? 1 : 0;
        k_zero_agg<<<nelem_blocks, 256>>>();
        k_msg<<<(NE + 31) / 32, 256>>>(node, ei, first);
        k_xin<<<nelem_blocks, 256>>>(bias);
        k_grugemm<<<(NN + 31) / 32, 192>>>(node, W_ih, W_hh, first);
        k_gates<<<nelem_blocks, 256>>>(node, b_ih, b_hh, first);
    }
    k_final<<<nelem_blocks, 256>>>(node, out);
}

// round 9
// speedup vs baseline: 3.2625x; 1.3376x over previous
#include <cuda_runtime.h>
#include <cuda_fp16.h>
#include <math.h>
#include <stdint.h>

#define NN 50000
#define NE 100000
#define D  64
#define F  128
#define DD 4096
#define EPSV 1e-5f
#define ECHUNK 25600   // multiple of 128 (GEMM tile rows); 4 chunks cover 102400 >= NE
#define NEPAD 100096   // NE rounded up to 128
#define MBLK 782       // NEPAD / 128
#define GY 37          // m-slices: 32*37 = 1184 CTAs = 8 * 148

// ---------------- scratch (static device globals; no runtime alloc) ----------------
__device__ __align__(16) __half g_raw0[(size_t)ECHUNK * DD];
__device__ __align__(16) __half g_raw1[(size_t)ECHUNK * DD];
__device__ __align__(16) __half g_raw2[(size_t)ECHUNK * DD];
__device__ __align__(16) __half g_raw3[(size_t)ECHUNK * DD];

__device__ __forceinline__ __half* raw_row(int e) {
    int c = e / ECHUNK;
    int r = e - c * ECHUNK;
    __half* base = (c == 0) ? g_raw0 : (c == 1) ? g_raw1 : (c == 2) ? g_raw2 : g_raw3;
    return base + (size_t)r * DD;
}

__device__ __align__(16) __half g_Ah[(size_t)NEPAD * F];   // 25.6 MB
__device__ __align__(16) __half g_Bh[(size_t)F * DD];      // 1 MB

__device__ __align__(16) float g_colsum[DD];
__device__ __align__(16) float g_colsq[DD];
__device__ __align__(16) float g_a[DD];
__device__ __align__(16) float g_c[DD];
__device__ __align__(16) float g_cnt[NN];
__device__ __align__(16) float g_inv[NN];
__device__ __align__(16) float g_agg[NN * D];
__device__ __align__(16) float g_xin[NN * D];
__device__ __align__(16) float g_node[NN * D];
__device__ __align__(16) float g_acc[NN * D];
__device__ __align__(16) float g_gi[(size_t)NN * 3 * D];
__device__ __align__(16) float g_gh[(size_t)NN * 3 * D];

struct alignas(8) H4 { __half2 x, y; };

// ---------------- zero / count helpers ----------------
__global__ void k_zero_pre() {
    int i = blockIdx.x * 256 + threadIdx.x;
    if (i < DD) { g_colsum[i] = 0.f; g_colsq[i] = 0.f; }
    if (i < NN) g_cnt[i] = 0.f;
}

__global__ void k_zero_agg() {
    int i = blockIdx.x * 256 + threadIdx.x;
    if (i < NN * D) g_agg[i] = 0.f;
}

__global__ void k_count(const int* __restrict__ ei) {
    int e = blockIdx.x * 256 + threadIdx.x;
    if (e < NE) atomicAdd(&g_cnt[ei[NE + e]], 1.0f);
}

__global__ void k_inv() {
    int i = blockIdx.x * 256 + threadIdx.x;
    if (i < NN) g_inv[i] = 1.0f / fmaxf(g_cnt[i], 1.0f);
}

// ---------------- fp32 -> fp16 pre-conversion ----------------
__global__ void k_toh_A(const float* __restrict__ A) {
    int i = blockIdx.x * 256 + threadIdx.x;   // one per 8 elems
    if (i >= NEPAD * F / 8) return;
    int r = i / (F / 8);
    H4 h0, h1;
    if (r < NE) {
        const float4* s = reinterpret_cast<const float4*>(A) + (size_t)i * 2;
        float4 v0 = s[0], v1 = s[1];
        h0.x = __floats2half2_rn(v0.x, v0.y); h0.y = __floats2half2_rn(v0.z, v0.w);
        h1.x = __floats2half2_rn(v1.x, v1.y); h1.y = __floats2half2_rn(v1.z, v1.w);
    } else {
        h0.x = h0.y = h1.x = h1.y = __floats2half2_rn(0.f, 0.f);
    }
    H4* d = reinterpret_cast<H4*>(g_Ah) + (size_t)i * 2;
    d[0] = h0; d[1] = h1;
}

__global__ void k_toh_B(const float* __restrict__ B) {
    int i = blockIdx.x * 256 + threadIdx.x;
    if (i >= F * DD / 8) return;
    const float4* s = reinterpret_cast<const float4*>(B) + (size_t)i * 2;
    float4 v0 = s[0], v1 = s[1];
    H4 h0, h1;
    h0.x = __floats2half2_rn(v0.x, v0.y); h0.y = __floats2half2_rn(v0.z, v0.w);
    h1.x = __floats2half2_rn(v1.x, v1.y); h1.y = __floats2half2_rn(v1.z, v1.w);
    H4* d = reinterpret_cast<H4*>(g_Bh) + (size_t)i * 2;
    d[0] = h0; d[1] = h1;
}

// ---------------- tensor-core GEMM helpers ----------------
__device__ __forceinline__ void ldsm_x4(uint32_t& r0, uint32_t& r1, uint32_t& r2, uint32_t& r3,
                                        uint32_t addr) {
    asm volatile("ldmatrix.sync.aligned.m8n8.x4.shared.b16 {%0,%1,%2,%3}, [%4];"
                 : "=r"(r0), "=r"(r1), "=r"(r2), "=r"(r3) : "r"(addr));
}
__device__ __forceinline__ void ldsm_x4_t(uint32_t& r0, uint32_t& r1, uint32_t& r2, uint32_t& r3,
                                          uint32_t addr) {
    asm volatile("ldmatrix.sync.aligned.m8n8.x4.trans.shared.b16 {%0,%1,%2,%3}, [%4];"
                 : "=r"(r0), "=r"(r1), "=r"(r2), "=r"(r3) : "r"(addr));
}
__device__ __forceinline__ void mma16816(float* c, const uint32_t* a, const uint32_t* b) {
    asm volatile(
        "mma.sync.aligned.m16n8k16.row.col.f32.f16.f16.f32 "
        "{%0,%1,%2,%3}, {%4,%5,%6,%7}, {%8,%9}, {%0,%1,%2,%3};"
        : "+f"(c[0]), "+f"(c[1]), "+f"(c[2]), "+f"(c[3])
        : "r"(a[0]), "r"(a[1]), "r"(a[2]), "r"(a[3]), "r"(b[0]), "r"(b[1]));
}
__device__ __forceinline__ void cpasync16(uint32_t smem, const void* gptr) {
    asm volatile("cp.async.cg.shared.global [%0], [%1], 16;" :: "r"(smem), "l"(gptr));
}

// ---------------- big GEMM: raw = A_h[NE,128] @ B_h[128,4096] + col stats ----
// Persistent n-strip CTAs: each CTA fixes n0 (128 cols), loads B once (kept in
// REGISTERS as ldmatrix fragments), loops m-blocks with double-buffered cp.async
// A prefetch. C staged through recycled B SMEM for coalesced fp16 stores.
// BN stats accumulate in registers, reduced once per CTA.
#define AS_STRIDE 136   // halves: 272B rows -> 4-bank rotation, conflict-free
#define BS_STRIDE 136
#define CS_STRIDE 136
#define TILE_B (128 * 136 * 2)          // 34816 B
#define GEMM_SMEM (TILE_B * 3 + 1024)
__global__ __launch_bounds__(256) void k_gemm_edge() {
    extern __shared__ __align__(16) unsigned char sm[];
    __half* As0 = (__half*)sm;                       // A buf 0 [128][136]
    __half* As1 = (__half*)(sm + TILE_B);            // A buf 1
    __half* BCs = (__half*)(sm + TILE_B * 2);        // B tile, then C staging
    float* csum_s = (float*)(sm + TILE_B * 3);       // [128]
    float* csq_s  = csum_s + 128;

    int tid = threadIdx.x;
    int warp = tid >> 5, lane = tid & 31;
    int wm = warp & 1, wn = warp >> 1;      // 2 (m) x 4 (n, 32-wide)
    int gid = lane >> 2, tig = lane & 3;
    int n0 = blockIdx.x * 128;
    int mb0 = blockIdx.y;                   // m-blocks: mb0, mb0+GY, ...

    uint32_t a_sb[2] = { (uint32_t)__cvta_generic_to_shared(As0),
                         (uint32_t)__cvta_generic_to_shared(As1) };
    uint32_t bc_sb = (uint32_t)__cvta_generic_to_shared(BCs);

    // ---- prolog: load B tile + A(mb0) in one group ----
#pragma unroll
    for (int it = 0; it < 8; it++) {
        int idx = it * 256 + tid;
        int r = idx >> 4, c16 = idx & 15;
        cpasync16(bc_sb + (r * BS_STRIDE + c16 * 8) * 2,
                  g_Bh + (size_t)r * DD + n0 + c16 * 8);
    }
#pragma unroll
    for (int it = 0; it < 8; it++) {
        int idx = it * 256 + tid;
        int r = idx >> 4, c16 = idx & 15;
        cpasync16(a_sb[0] + (r * AS_STRIDE + c16 * 8) * 2,
                  g_Ah + (size_t)(mb0 * 128 + r) * F + c16 * 8);
    }
    asm volatile("cp.async.commit_group;");
    if (tid < 128) { csum_s[tid] = 0.f; csq_s[tid] = 0.f; }
    asm volatile("cp.async.wait_group 0;");
    __syncthreads();

    // ---- B fragments -> registers (loop-invariant) ----
    uint32_t bfr[8][4][2];
#pragma unroll
    for (int ks = 0; ks < 8; ks++) {
#pragma unroll
        for (int hb = 0; hb < 2; hb++) {
            int krow = ks * 16 + (lane & 15);
            int ncol = wn * 32 + hb * 16 + ((lane >> 4) << 3);
            uint32_t addr = bc_sb + (krow * BS_STRIDE + ncol) * 2;
            ldsm_x4_t(bfr[ks][2 * hb][0], bfr[ks][2 * hb][1],
                      bfr[ks][2 * hb + 1][0], bfr[ks][2 * hb + 1][1], addr);
        }
    }
    __syncthreads();   // BCs now free for C staging

    float csum_r[8], csq_r[8];
#pragma unroll
    for (int j = 0; j < 8; j++) { csum_r[j] = 0.f; csq_r[j] = 0.f; }

    int buf = 0;
    for (int mb = mb0; mb < MBLK; mb += GY) {
        int mbn = mb + GY;
        // prefetch next A into other buffer
        if (mbn < MBLK) {
#pragma unroll
            for (int it = 0; it < 8; it++) {
                int idx = it * 256 + tid;
                int r = idx >> 4, c16 = idx & 15;
                cpasync16(a_sb[buf ^ 1] + (r * AS_STRIDE + c16 * 8) * 2,
                          g_Ah + (size_t)(mbn * 128 + r) * F + c16 * 8);
            }
            asm volatile("cp.async.commit_group;");
            asm volatile("cp.async.wait_group 1;");
        } else {
            asm volatile("cp.async.wait_group 0;");
        }
        __syncthreads();

        float c[4][4][4];
#pragma unroll
        for (int i = 0; i < 4; i++)
#pragma unroll
            for (int j = 0; j < 4; j++)
#pragma unroll
                for (int q = 0; q < 4; q++) c[i][j][q] = 0.f;

        uint32_t a_cur = a_sb[buf];
#pragma unroll
        for (int ks = 0; ks < 8; ks++) {
            uint32_t a[4][4];
#pragma unroll
            for (int mi = 0; mi < 4; mi++) {
                int row = wm * 64 + mi * 16 + (lane & 15);
                int kof = ks * 16 + ((lane >> 4) << 3);
                ldsm_x4(a[mi][0], a[mi][1], a[mi][2], a[mi][3],
                        a_cur + (row * AS_STRIDE + kof) * 2);
            }
#pragma unroll
            for (int mi = 0; mi < 4; mi++)
#pragma unroll
                for (int ni = 0; ni < 4; ni++)
                    mma16816(c[mi][ni], a[mi], bfr[ks][ni]);
        }
        __syncthreads();   // prev C store (if any) fully drained; safe to restage

        // stage C + per-thread stats
#pragma unroll
        for (int mi = 0; mi < 4; mi++) {
#pragma unroll
            for (int ni = 0; ni < 4; ni++) {
                int row0 = wm * 64 + mi * 16 + gid;
                int col = wn * 32 + ni * 8 + tig * 2;
                *reinterpret_cast<__half2*>(&BCs[row0 * CS_STRIDE + col]) =
                    __floats2half2_rn(c[mi][ni][0], c[mi][ni][1]);
                *reinterpret_cast<__half2*>(&BCs[(row0 + 8) * CS_STRIDE + col]) =
                    __floats2half2_rn(c[mi][ni][2], c[mi][ni][3]);
                csum_r[ni * 2]     += c[mi][ni][0] + c[mi][ni][2];
                csum_r[ni * 2 + 1] += c[mi][ni][1] + c[mi][ni][3];
                csq_r[ni * 2]      += c[mi][ni][0] * c[mi][ni][0] + c[mi][ni][2] * c[mi][ni][2];
                csq_r[ni * 2 + 1]  += c[mi][ni][1] * c[mi][ni][1] + c[mi][ni][3] * c[mi][ni][3];
            }
        }
        __syncthreads();

        // coalesced fp16 store: 2 threads per row, 64 halves (128B) each
        {
            int r = tid >> 1, seg = tid & 1;
            int m = mb * 128 + r;
            if (m < NE) {
                __half* dst = raw_row(m) + n0 + seg * 64;
                const __half* src = &BCs[r * CS_STRIDE + seg * 64];
#pragma unroll
                for (int q = 0; q < 8; q++)
                    *reinterpret_cast<uint4*>(&dst[q * 8]) =
                        *reinterpret_cast<const uint4*>(&src[q * 8]);
            }
        }
        __syncthreads();
        buf ^= 1;
    }

    // ---- per-CTA stats reduction -> global ----
#pragma unroll
    for (int ni = 0; ni < 4; ni++) {
#pragma unroll
        for (int t = 0; t < 2; t++) {
            int col = wn * 32 + ni * 8 + tig * 2 + t;
            atomicAdd(&csum_s[col], csum_r[ni * 2 + t]);
            atomicAdd(&csq_s[col],  csq_r[ni * 2 + t]);
        }
    }
    __syncthreads();
    if (tid < 128) {
        atomicAdd(&g_colsum[n0 + tid], csum_s[tid]);
        atomicAdd(&g_colsq[n0 + tid],  csq_s[tid]);
    }
}

// ---------------- BN coefficients ----------------
__global__ void k_bncoef(const float* __restrict__ gamma, const float* __restrict__ beta) {
    int i = blockIdx.x * 256 + threadIdx.x;
    if (i < DD) {
        float mu  = g_colsum[i] * (1.0f / NE);
        float var = g_colsq[i] * (1.0f / NE) - mu * mu;
        float a = gamma[i] * rsqrtf(var + EPSV);
        g_a[i] = a;
        g_c[i] = beta[i] - mu * a;
    }
}

// ---------------- message + scatter: agg[dst] += x[src] . (a*raw + c) -------------
__global__ __launch_bounds__(256) void k_msg(const float* __restrict__ x0,
                                             const int* __restrict__ ei,
                                             int first) {
    __shared__ __align__(16) float a_s[DD];
    __shared__ __align__(16) float c_s[DD];
    __shared__ float xs[4][D];

    const float* __restrict__ x = first ? x0 : (const float*)g_node;
    int tid = threadIdx.x;
    for (int i = tid * 4; i < DD; i += 1024) {
        *reinterpret_cast<float4*>(&a_s[i]) = *reinterpret_cast<const float4*>(&g_a[i]);
        *reinterpret_cast<float4*>(&c_s[i]) = *reinterpret_cast<const float4*>(&g_c[i]);
    }
    __syncthreads();

    int sub = tid >> 6, k = tid & 63;
    int ebase = blockIdx.x * 32;

    for (int it = 0; it < 8; it++) {
        int e = ebase + it * 4 + sub;
        bool valid = e < NE;
        int dst = 0;
        if (valid) {
            int src = ei[e];
            dst = ei[NE + e];
            xs[sub][k] = x[src * D + k];
        }
        __syncthreads();
        if (valid) {
            const __half* rp = raw_row(e) + k;
            float acc0 = 0.f, acc1 = 0.f;
#pragma unroll
            for (int d = 0; d < D; d += 2) {
                int i0 = d * 64 + k;
                float r0 = __half2float(rp[d * 64]);
                float r1 = __half2float(rp[(d + 1) * 64]);
                acc0 = fmaf(xs[sub][d],     fmaf(a_s[i0],      r0, c_s[i0]),      acc0);
                acc1 = fmaf(xs[sub][d + 1], fmaf(a_s[i0 + 64], r1, c_s[i0 + 64]), acc1);
            }
            atomicAdd(&g_agg[dst * D + k], acc0 + acc1);
        }
        __syncthreads();
    }
}

// ---------------- node_in = relu(agg/cnt + bias) ----------------
__global__ void k_xin(const float* __restrict__ bias) {
    int i = blockIdx.x * 256 + threadIdx.x;
    if (i < NN * D) {
        float v = fmaf(g_agg[i], g_inv[i >> 6], bias[i & 63]);
        g_xin[i] = fmaxf(v, 0.f);
    }
}

// ---------------- GRU GEMVs: gi = xin@W_ih^T, gh = h@W_hh^T ----------------
__global__ __launch_bounds__(192) void k_grugemm(const float* __restrict__ x0,
                                                 const float* __restrict__ Wih,
                                                 const float* __restrict__ Whh,
                                                 int first) {
    __shared__ float4 xs4[32][16];
    __shared__ float4 hs4[32][16];
    const float* __restrict__ h = first ? x0 : (const float*)g_node;

    int tid = threadIdx.x;
    int base = blockIdx.x * 32;

    for (int f4 = tid; f4 < 512; f4 += 192) {
        int nb = base + (f4 >> 4);
        int c = f4 & 15;
        float4 v = make_float4(0.f, 0.f, 0.f, 0.f), w = v;
        if (nb < NN) {
            v = *reinterpret_cast<const float4*>(&g_xin[nb * D + c * 4]);
            w = *reinterpret_cast<const float4*>(&h[nb * D + c * 4]);
        }
        xs4[f4 >> 4][c] = v;
        hs4[f4 >> 4][c] = w;
    }
    __syncthreads();

    int g = tid;  // 0..191
    int nmax = NN - base; if (nmax > 32) nmax = 32;

    float4 wr[16];
#pragma unroll
    for (int q = 0; q < 16; q++) wr[q] = reinterpret_cast<const float4*>(Wih)[g * 16 + q];
    for (int nn = 0; nn < nmax; nn++) {
        float acc = 0.f;
#pragma unroll
        for (int q = 0; q < 16; q++) {
            float4 xv = xs4[nn][q]; float4 wv = wr[q];
            acc = fmaf(xv.x, wv.x, acc); acc = fmaf(xv.y, wv.y, acc);
            acc = fmaf(xv.z, wv.z, acc); acc = fmaf(xv.w, wv.w, acc);
        }
        g_gi[(size_t)(base + nn) * 192 + g] = acc;
    }
#pragma unroll
    for (int q = 0; q < 16; q++) wr[q] = reinterpret_cast<const float4*>(Whh)[g * 16 + q];
    for (int nn = 0; nn < nmax; nn++) {
        float acc = 0.f;
#pragma unroll
        for (int q = 0; q < 16; q++) {
            float4 xv = hs4[nn][q]; float4 wv = wr[q];
            acc = fmaf(xv.x, wv.x, acc); acc = fmaf(xv.y, wv.y, acc);
            acc = fmaf(xv.z, wv.z, acc); acc = fmaf(xv.w, wv.w, acc);
        }
        g_gh[(size_t)(base + nn) * 192 + g] = acc;
    }
}

// ---------------- GRU gates + output accumulation ----------------
__global__ void k_gates(const float* __restrict__ x0,
                        const float* __restrict__ b_ih,
                        const float* __restrict__ b_hh,
                        int first) {
    int i = blockIdx.x * 256 + threadIdx.x;
    if (i >= NN * D) return;
    int n = i >> 6, j = i & 63;
    size_t o = (size_t)n * 192 + j;

    float ir = g_gi[o]       + b_ih[j];
    float iz = g_gi[o + 64]  + b_ih[64 + j];
    float in = g_gi[o + 128] + b_ih[128 + j];
    float hr = g_gh[o]       + b_hh[j];
    float hz = g_gh[o + 64]  + b_hh[64 + j];
    float hn = g_gh[o + 128] + b_hh[128 + j];

    float r = 1.0f / (1.0f + expf(-(ir + hr)));
    float z = 1.0f / (1.0f + expf(-(iz + hz)));
    float nv = tanhf(fmaf(r, hn, in));

    float hold = first ? x0[i] : g_node[i];
    float hnew = fmaf(z, hold - nv, nv);   // (1-z)*n + z*h

    if (first) g_acc[i] = hold;
    else       g_acc[i] += hold;
    g_node[i] = hnew;
}

// ---------------- out = (node0+node1+node2+node3)/4 + x0 ----------------
__global__ void k_final(const float* __restrict__ x0, float* __restrict__ out) {
    int i = blockIdx.x * 256 + threadIdx.x;
    if (i < NN * D) out[i] = (g_acc[i] + g_node[i]) * 0.25f + x0[i];
}

// ---------------- launcher ----------------
extern "C" void kernel_launch(void* const* d_in, const int* in_sizes, int n_in,
                              void* d_out, int out_size) {
    const float* node   = (const float*)d_in[0];
    const int*   ei     = (const int*)d_in[1];     // int32 (JAX x64 disabled)
    const float* edge   = (const float*)d_in[2];
    const float* W_edge = (const float*)d_in[3];
    const float* gamma  = (const float*)d_in[4];
    const float* beta   = (const float*)d_in[5];
    const float* bias   = (const float*)d_in[6];
    const float* W_ih   = (const float*)d_in[7];
    const float* W_hh   = (const float*)d_in[8];
    const float* b_ih   = (const float*)d_in[9];
    const float* b_hh   = (const float*)d_in[10];
    float* out = (float*)d_out;

    cudaFuncSetAttribute(k_gemm_edge, cudaFuncAttributeMaxDynamicSharedMemorySize, GEMM_SMEM);

    k_zero_pre<<<196, 256>>>();
    k_count<<<(NE + 255) / 256, 256>>>(ei);
    k_inv<<<196, 256>>>();

    k_toh_A<<<(NEPAD * F / 8 + 255) / 256, 256>>>(edge);
    k_toh_B<<<(F * DD / 8 + 255) / 256, 256>>>(W_edge);

    dim3 gg(DD / 128, GY);
    k_gemm_edge<<<gg, 256, GEMM_SMEM>>>();
    k_bncoef<<<16, 256>>>(gamma, beta);

    // only 3 propagation steps needed: out = x0 + mean(node_0..node_3);
    // the reference's 4th GRU update is dead code.
    int nelem_blocks = (NN * D + 255) / 256;
    for (int s = 0; s < 3; s++) {
        int first = (s == 0) ? 1 : 0;
        k_zero_agg<<<nelem_blocks, 256>>>();
        k_msg<<<(NE + 31) / 32, 256>>>(node, ei, first);
        k_xin<<<nelem_blocks, 256>>>(bias);
        k_grugemm<<<(NN + 31) / 32, 192>>>(node, W_ih, W_hh, first);
        k_gates<<<nelem_blocks, 256>>>(node, b_ih, b_hh, first);
    }
    k_final<<<nelem_blocks, 256>>>(node, out);
}

// round 10
// speedup vs baseline: 3.5849x; 1.0988x over previous
#include <cuda_runtime.h>
#include <cuda_fp16.h>
#include <math.h>
#include <stdint.h>

#define NN 50000
#define NE 100000
#define D  64
#define F  128
#define DD 4096
#define EPSV 1e-5f
#define ECHUNK 25600   // multiple of 128 (GEMM tile rows); 4 chunks cover 102400 >= NE
#define NEPAD 100096   // NE rounded up to 128
#define MBLK 782       // NEPAD / 128
#define GY 37          // m-slices: 32*37 = 1184 CTAs = 8 * 148

// ---------------- scratch (static device globals; no runtime alloc) ----------------
__device__ __align__(16) __half g_raw0[(size_t)ECHUNK * DD];
__device__ __align__(16) __half g_raw1[(size_t)ECHUNK * DD];
__device__ __align__(16) __half g_raw2[(size_t)ECHUNK * DD];
__device__ __align__(16) __half g_raw3[(size_t)ECHUNK * DD];

__device__ __forceinline__ __half* raw_row(int e) {
    int c = e / ECHUNK;
    int r = e - c * ECHUNK;
    __half* base = (c == 0) ? g_raw0 : (c == 1) ? g_raw1 : (c == 2) ? g_raw2 : g_raw3;
    return base + (size_t)r * DD;
}

__device__ __align__(16) __half g_Ah[(size_t)NEPAD * F];   // 25.6 MB
__device__ __align__(16) __half g_Bh[(size_t)F * DD];      // 1 MB

__device__ __align__(16) float g_colsum[DD];
__device__ __align__(16) float g_colsq[DD];
__device__ __align__(16) float g_a[DD];
__device__ __align__(16) float g_c[DD];
__device__ __align__(16) float g_cnt[NN];
__device__ __align__(16) float g_inv[NN];
__device__ __align__(16) float g_agg[NN * D];
__device__ __align__(16) float g_xin[NN * D];
__device__ __align__(16) float g_node[NN * D];
__device__ __align__(16) float g_acc[NN * D];

struct alignas(8) H4 { __half2 x, y; };

// ---------------- zero / count helpers ----------------
__global__ void k_zero_pre() {
    int i = blockIdx.x * 256 + threadIdx.x;
    if (i < DD) { g_colsum[i] = 0.f; g_colsq[i] = 0.f; }
    if (i < NN) g_cnt[i] = 0.f;
    if (i < NN * D) g_agg[i] = 0.f;
}

__global__ void k_count(const int* __restrict__ ei) {
    int e = blockIdx.x * 256 + threadIdx.x;
    if (e < NE) atomicAdd(&g_cnt[ei[NE + e]], 1.0f);
}

__global__ void k_inv() {
    int i = blockIdx.x * 256 + threadIdx.x;
    if (i < NN) g_inv[i] = 1.0f / fmaxf(g_cnt[i], 1.0f);
}

// ---------------- fp32 -> fp16 pre-conversion ----------------
__global__ void k_toh_A(const float* __restrict__ A) {
    int i = blockIdx.x * 256 + threadIdx.x;   // one per 8 elems
    if (i >= NEPAD * F / 8) return;
    int r = i / (F / 8);
    H4 h0, h1;
    if (r < NE) {
        const float4* s = reinterpret_cast<const float4*>(A) + (size_t)i * 2;
        float4 v0 = s[0], v1 = s[1];
        h0.x = __floats2half2_rn(v0.x, v0.y); h0.y = __floats2half2_rn(v0.z, v0.w);
        h1.x = __floats2half2_rn(v1.x, v1.y); h1.y = __floats2half2_rn(v1.z, v1.w);
    } else {
        h0.x = h0.y = h1.x = h1.y = __floats2half2_rn(0.f, 0.f);
    }
    H4* d = reinterpret_cast<H4*>(g_Ah) + (size_t)i * 2;
    d[0] = h0; d[1] = h1;
}

__global__ void k_toh_B(const float* __restrict__ B) {
    int i = blockIdx.x * 256 + threadIdx.x;
    if (i >= F * DD / 8) return;
    const float4* s = reinterpret_cast<const float4*>(B) + (size_t)i * 2;
    float4 v0 = s[0], v1 = s[1];
    H4 h0, h1;
    h0.x = __floats2half2_rn(v0.x, v0.y); h0.y = __floats2half2_rn(v0.z, v0.w);
    h1.x = __floats2half2_rn(v1.x, v1.y); h1.y = __floats2half2_rn(v1.z, v1.w);
    H4* d = reinterpret_cast<H4*>(g_Bh) + (size_t)i * 2;
    d[0] = h0; d[1] = h1;
}

// ---------------- tensor-core GEMM helpers ----------------
__device__ __forceinline__ void ldsm_x4(uint32_t& r0, uint32_t& r1, uint32_t& r2, uint32_t& r3,
                                        uint32_t addr) {
    asm volatile("ldmatrix.sync.aligned.m8n8.x4.shared.b16 {%0,%1,%2,%3}, [%4];"
                 : "=r"(r0), "=r"(r1), "=r"(r2), "=r"(r3) : "r"(addr));
}
__device__ __forceinline__ void ldsm_x4_t(uint32_t& r0, uint32_t& r1, uint32_t& r2, uint32_t& r3,
                                          uint32_t addr) {
    asm volatile("ldmatrix.sync.aligned.m8n8.x4.trans.shared.b16 {%0,%1,%2,%3}, [%4];"
                 : "=r"(r0), "=r"(r1), "=r"(r2), "=r"(r3) : "r"(addr));
}
__device__ __forceinline__ void mma16816(float* c, const uint32_t* a, const uint32_t* b) {
    asm volatile(
        "mma.sync.aligned.m16n8k16.row.col.f32.f16.f16.f32 "
        "{%0,%1,%2,%3}, {%4,%5,%6,%7}, {%8,%9}, {%0,%1,%2,%3};"
        : "+f"(c[0]), "+f"(c[1]), "+f"(c[2]), "+f"(c[3])
        : "r"(a[0]), "r"(a[1]), "r"(a[2]), "r"(a[3]), "r"(b[0]), "r"(b[1]));
}
__device__ __forceinline__ void cpasync16(uint32_t smem, const void* gptr) {
    asm volatile("cp.async.cg.shared.global [%0], [%1], 16;" :: "r"(smem), "l"(gptr));
}

// ---------------- big GEMM: raw = A_h[NE,128] @ B_h[128,4096] + col stats ----
// Persistent n-strip CTAs; B in registers; A double-buffered cp.async.
#define AS_STRIDE 136
#define BS_STRIDE 136
#define CS_STRIDE 136
#define TILE_B (128 * 136 * 2)          // 34816 B
#define GEMM_SMEM (TILE_B * 3 + 1024)
__global__ __launch_bounds__(256) void k_gemm_edge() {
    extern __shared__ __align__(16) unsigned char sm[];
    __half* As0 = (__half*)sm;
    __half* As1 = (__half*)(sm + TILE_B);
    __half* BCs = (__half*)(sm + TILE_B * 2);
    float* csum_s = (float*)(sm + TILE_B * 3);
    float* csq_s  = csum_s + 128;

    int tid = threadIdx.x;
    int warp = tid >> 5, lane = tid & 31;
    int wm = warp & 1, wn = warp >> 1;
    int gid = lane >> 2, tig = lane & 3;
    int n0 = blockIdx.x * 128;
    int mb0 = blockIdx.y;

    uint32_t a_sb[2] = { (uint32_t)__cvta_generic_to_shared(As0),
                         (uint32_t)__cvta_generic_to_shared(As1) };
    uint32_t bc_sb = (uint32_t)__cvta_generic_to_shared(BCs);

#pragma unroll
    for (int it = 0; it < 8; it++) {
        int idx = it * 256 + tid;
        int r = idx >> 4, c16 = idx & 15;
        cpasync16(bc_sb + (r * BS_STRIDE + c16 * 8) * 2,
                  g_Bh + (size_t)r * DD + n0 + c16 * 8);
    }
#pragma unroll
    for (int it = 0; it < 8; it++) {
        int idx = it * 256 + tid;
        int r = idx >> 4, c16 = idx & 15;
        cpasync16(a_sb[0] + (r * AS_STRIDE + c16 * 8) * 2,
                  g_Ah + (size_t)(mb0 * 128 + r) * F + c16 * 8);
    }
    asm volatile("cp.async.commit_group;");
    if (tid < 128) { csum_s[tid] = 0.f; csq_s[tid] = 0.f; }
    asm volatile("cp.async.wait_group 0;");
    __syncthreads();

    uint32_t bfr[8][4][2];
#pragma unroll
    for (int ks = 0; ks < 8; ks++) {
#pragma unroll
        for (int hb = 0; hb < 2; hb++) {
            int krow = ks * 16 + (lane & 15);
            int ncol = wn * 32 + hb * 16 + ((lane >> 4) << 3);
            uint32_t addr = bc_sb + (krow * BS_STRIDE + ncol) * 2;
            ldsm_x4_t(bfr[ks][2 * hb][0], bfr[ks][2 * hb][1],
                      bfr[ks][2 * hb + 1][0], bfr[ks][2 * hb + 1][1], addr);
        }
    }
    __syncthreads();

    float csum_r[8], csq_r[8];
#pragma unroll
    for (int j = 0; j < 8; j++) { csum_r[j] = 0.f; csq_r[j] = 0.f; }

    int buf = 0;
    for (int mb = mb0; mb < MBLK; mb += GY) {
        int mbn = mb + GY;
        if (mbn < MBLK) {
#pragma unroll
            for (int it = 0; it < 8; it++) {
                int idx = it * 256 + tid;
                int r = idx >> 4, c16 = idx & 15;
                cpasync16(a_sb[buf ^ 1] + (r * AS_STRIDE + c16 * 8) * 2,
                          g_Ah + (size_t)(mbn * 128 + r) * F + c16 * 8);
            }
            asm volatile("cp.async.commit_group;");
            asm volatile("cp.async.wait_group 1;");
        } else {
            asm volatile("cp.async.wait_group 0;");
        }
        __syncthreads();

        float c[4][4][4];
#pragma unroll
        for (int i = 0; i < 4; i++)
#pragma unroll
            for (int j = 0; j < 4; j++)
#pragma unroll
                for (int q = 0; q < 4; q++) c[i][j][q] = 0.f;

        uint32_t a_cur = a_sb[buf];
#pragma unroll
        for (int ks = 0; ks < 8; ks++) {
            uint32_t a[4][4];
#pragma unroll
            for (int mi = 0; mi < 4; mi++) {
                int row = wm * 64 + mi * 16 + (lane & 15);
                int kof = ks * 16 + ((lane >> 4) << 3);
                ldsm_x4(a[mi][0], a[mi][1], a[mi][2], a[mi][3],
                        a_cur + (row * AS_STRIDE + kof) * 2);
            }
#pragma unroll
            for (int mi = 0; mi < 4; mi++)
#pragma unroll
                for (int ni = 0; ni < 4; ni++)
                    mma16816(c[mi][ni], a[mi], bfr[ks][ni]);
        }
        __syncthreads();

#pragma unroll
        for (int mi = 0; mi < 4; mi++) {
#pragma unroll
            for (int ni = 0; ni < 4; ni++) {
                int row0 = wm * 64 + mi * 16 + gid;
                int col = wn * 32 + ni * 8 + tig * 2;
                *reinterpret_cast<__half2*>(&BCs[row0 * CS_STRIDE + col]) =
                    __floats2half2_rn(c[mi][ni][0], c[mi][ni][1]);
                *reinterpret_cast<__half2*>(&BCs[(row0 + 8) * CS_STRIDE + col]) =
                    __floats2half2_rn(c[mi][ni][2], c[mi][ni][3]);
                csum_r[ni * 2]     += c[mi][ni][0] + c[mi][ni][2];
                csum_r[ni * 2 + 1] += c[mi][ni][1] + c[mi][ni][3];
                csq_r[ni * 2]      += c[mi][ni][0] * c[mi][ni][0] + c[mi][ni][2] * c[mi][ni][2];
                csq_r[ni * 2 + 1]  += c[mi][ni][1] * c[mi][ni][1] + c[mi][ni][3] * c[mi][ni][3];
            }
        }
        __syncthreads();

        {
            int r = tid >> 1, seg = tid & 1;
            int m = mb * 128 + r;
            if (m < NE) {
                __half* dst = raw_row(m) + n0 + seg * 64;
                const __half* src = &BCs[r * CS_STRIDE + seg * 64];
#pragma unroll
                for (int q = 0; q < 8; q++)
                    *reinterpret_cast<uint4*>(&dst[q * 8]) =
                        *reinterpret_cast<const uint4*>(&src[q * 8]);
            }
        }
        __syncthreads();
        buf ^= 1;
    }

#pragma unroll
    for (int ni = 0; ni < 4; ni++) {
#pragma unroll
        for (int t = 0; t < 2; t++) {
            int col = wn * 32 + ni * 8 + tig * 2 + t;
            atomicAdd(&csum_s[col], csum_r[ni * 2 + t]);
            atomicAdd(&csq_s[col],  csq_r[ni * 2 + t]);
        }
    }
    __syncthreads();
    if (tid < 128) {
        atomicAdd(&g_colsum[n0 + tid], csum_s[tid]);
        atomicAdd(&g_colsq[n0 + tid],  csq_s[tid]);
    }
}

// ---------------- BN coefficients ----------------
__global__ void k_bncoef(const float* __restrict__ gamma, const float* __restrict__ beta) {
    int i = blockIdx.x * 256 + threadIdx.x;
    if (i < DD) {
        float mu  = g_colsum[i] * (1.0f / NE);
        float var = g_colsq[i] * (1.0f / NE) - mu * mu;
        float a = gamma[i] * rsqrtf(var + EPSV);
        g_a[i] = a;
        g_c[i] = beta[i] - mu * a;
    }
}

// ---------------- message + scatter: agg[dst] += x[src] . (a*raw + c) -------------
// warp-per-edge, no block barriers after staging; thread owns 2 adjacent columns.
__global__ __launch_bounds__(256) void k_msg(const float* __restrict__ x0,
                                             const int* __restrict__ ei,
                                             int first) {
    __shared__ __align__(16) float a_s[DD];
    __shared__ __align__(16) float c_s[DD];
    __shared__ float xs[8][D];

    const float* __restrict__ x = first ? x0 : (const float*)g_node;
    int tid = threadIdx.x;
    for (int i = tid * 4; i < DD; i += 1024) {
        *reinterpret_cast<float4*>(&a_s[i]) = *reinterpret_cast<const float4*>(&g_a[i]);
        *reinterpret_cast<float4*>(&c_s[i]) = *reinterpret_cast<const float4*>(&g_c[i]);
    }
    __syncthreads();

    int warp = tid >> 5, lane = tid & 31;
    int gw = blockIdx.x * 8 + warp;
    int k = lane * 2;

    for (int e = gw; e < NE; e += gridDim.x * 8) {
        int src = ei[e];
        int dst = ei[NE + e];
        xs[warp][lane]      = x[src * D + lane];
        xs[warp][lane + 32] = x[src * D + lane + 32];
        __syncwarp();

        const __half* rp = raw_row(e);
        float acc0 = 0.f, acc1 = 0.f;
#pragma unroll
        for (int d = 0; d < D; d++) {
            __half2 h = *reinterpret_cast<const __half2*>(rp + d * D + k);
            float2 r = __half22float2(h);
            float xv = xs[warp][d];
            int i0 = d * D + k;
            acc0 = fmaf(xv, fmaf(a_s[i0],     r.x, c_s[i0]),     acc0);
            acc1 = fmaf(xv, fmaf(a_s[i0 + 1], r.y, c_s[i0 + 1]), acc1);
        }
        atomicAdd(&g_agg[dst * D + k],     acc0);
        atomicAdd(&g_agg[dst * D + k + 1], acc1);
        __syncwarp();
    }
}

// ---------------- node_in = relu(agg/cnt + bias); reset agg for next sweep --------
__global__ void k_xin(const float* __restrict__ bias) {
    int i = blockIdx.x * 256 + threadIdx.x;
    if (i < NN * D) {
        float v = fmaf(g_agg[i], g_inv[i >> 6], bias[i & 63]);
        g_xin[i] = fmaxf(v, 0.f);
        g_agg[i] = 0.f;
    }
}

// ---------------- fused GRU: GEMVs in SMEM + gates + acc/out ----------------
// 192 threads, 32 nodes/block. gi/gh never touch global memory.
#define GRU_SMEM (2048 * 4 * 2 + 32 * 192 * 4 * 2)   // xs+hs + gi+gh = 65536 B
__global__ __launch_bounds__(192) void k_gru(const float* __restrict__ x0,
                                             const float* __restrict__ Wih,
                                             const float* __restrict__ Whh,
                                             const float* __restrict__ b_ih,
                                             const float* __restrict__ b_hh,
                                             float* __restrict__ out,
                                             int first, int last) {
    extern __shared__ __align__(16) unsigned char smg[];
    float* xs   = (float*)smg;                 // [32][64]
    float* hs   = xs + 2048;                   // [32][64]
    float* gi_s = hs + 2048;                   // [32][192]
    float* gh_s = gi_s + 32 * 192;             // [32][192]

    const float* __restrict__ h = first ? x0 : (const float*)g_node;
    int tid = threadIdx.x;
    int base = blockIdx.x * 32;

    for (int f4 = tid; f4 < 512; f4 += 192) {
        int nb = base + (f4 >> 4);
        float4 v = make_float4(0.f, 0.f, 0.f, 0.f), w = v;
        if (nb < NN) {
            v = *reinterpret_cast<const float4*>(&g_xin[nb * D + (f4 & 15) * 4]);
            w = *reinterpret_cast<const float4*>(&h[nb * D + (f4 & 15) * 4]);
        }
        *reinterpret_cast<float4*>(&xs[f4 * 4]) = v;
        *reinterpret_cast<float4*>(&hs[f4 * 4]) = w;
    }
    __syncthreads();

    // GEMV: thread g = one gate-row (0..191)
    {
        float4 wr[16];
#pragma unroll
        for (int q = 0; q < 16; q++) wr[q] = reinterpret_cast<const float4*>(Wih)[tid * 16 + q];
        for (int nn = 0; nn < 32; nn++) {
            float acc = 0.f;
#pragma unroll
            for (int q = 0; q < 16; q++) {
                float4 xv = *reinterpret_cast<float4*>(&xs[nn * D + q * 4]);
                float4 wv = wr[q];
                acc = fmaf(xv.x, wv.x, acc); acc = fmaf(xv.y, wv.y, acc);
                acc = fmaf(xv.z, wv.z, acc); acc = fmaf(xv.w, wv.w, acc);
            }
            gi_s[nn * 192 + tid] = acc;
        }
#pragma unroll
        for (int q = 0; q < 16; q++) wr[q] = reinterpret_cast<const float4*>(Whh)[tid * 16 + q];
        for (int nn = 0; nn < 32; nn++) {
            float acc = 0.f;
#pragma unroll
            for (int q = 0; q < 16; q++) {
                float4 xv = *reinterpret_cast<float4*>(&hs[nn * D + q * 4]);
                float4 wv = wr[q];
                acc = fmaf(xv.x, wv.x, acc); acc = fmaf(xv.y, wv.y, acc);
                acc = fmaf(xv.z, wv.z, acc); acc = fmaf(xv.w, wv.w, acc);
            }
            gh_s[nn * 192 + tid] = acc;
        }
    }
    __syncthreads();

    // gates
    for (int i = tid; i < 2048; i += 192) {
        int gidx = base * D + i;
        if (gidx >= NN * D) break;
        int nl = i >> 6, j = i & 63;

        float ir = gi_s[nl * 192 + j]       + b_ih[j];
        float iz = gi_s[nl * 192 + 64 + j]  + b_ih[64 + j];
        float in = gi_s[nl * 192 + 128 + j] + b_ih[128 + j];
        float hr = gh_s[nl * 192 + j]       + b_hh[j];
        float hz = gh_s[nl * 192 + 64 + j]  + b_hh[64 + j];
        float hn = gh_s[nl * 192 + 128 + j] + b_hh[128 + j];

        float r = 1.0f / (1.0f + expf(-(ir + hr)));
        float z = 1.0f / (1.0f + expf(-(iz + hz)));
        float nv = tanhf(fmaf(r, hn, in));

        float hold = hs[i];
        float hnew = fmaf(z, hold - nv, nv);   // (1-z)*n + z*h

        if (last) {
            out[gidx] = (g_acc[gidx] + hold + hnew) * 0.25f + x0[gidx];
        } else {
            if (first) g_acc[gidx] = hold;
            else       g_acc[gidx] += hold;
            g_node[gidx] = hnew;
        }
    }
}

// ---------------- launcher ----------------
extern "C" void kernel_launch(void* const* d_in, const int* in_sizes, int n_in,
                              void* d_out, int out_size) {
    const float* node   = (const float*)d_in[0];
    const int*   ei     = (const int*)d_in[1];     // int32 (JAX x64 disabled)
    const float* edge   = (const float*)d_in[2];
    const float* W_edge = (const float*)d_in[3];
    const float* gamma  = (const float*)d_in[4];
    const float* beta   = (const float*)d_in[5];
    const float* bias   = (const float*)d_in[6];
    const float* W_ih   = (const float*)d_in[7];
    const float* W_hh   = (const float*)d_in[8];
    const float* b_ih   = (const float*)d_in[9];
    const float* b_hh   = (const float*)d_in[10];
    float* out = (float*)d_out;

    cudaFuncSetAttribute(k_gemm_edge, cudaFuncAttributeMaxDynamicSharedMemorySize, GEMM_SMEM);
    cudaFuncSetAttribute(k_gru, cudaFuncAttributeMaxDynamicSharedMemorySize, GRU_SMEM);

    int nelem_blocks = (NN * D + 255) / 256;
    k_zero_pre<<<nelem_blocks, 256>>>();
    k_count<<<(NE + 255) / 256, 256>>>(ei);
    k_inv<<<196, 256>>>();

    k_toh_A<<<(NEPAD * F / 8 + 255) / 256, 256>>>(edge);
    k_toh_B<<<(F * DD / 8 + 255) / 256, 256>>>(W_edge);

    dim3 gg(DD / 128, GY);
    k_gemm_edge<<<gg, 256, GEMM_SMEM>>>();
    k_bncoef<<<16, 256>>>(gamma, beta);

    // only 3 propagation steps needed: out = x0 + mean(node_0..node_3);
    // the reference's 4th GRU update is dead code.
    for (int s = 0; s < 3; s++) {
        int first = (s == 0) ? 1 : 0;
        int last = (s == 2) ? 1 : 0;
        k_msg<<<1184, 256>>>(node, ei, first);
        k_xin<<<nelem_blocks, 256>>>(bias);
        k_gru<<<(NN + 31) / 32, 192, GRU_SMEM>>>(node, W_ih, W_hh, b_ih, b_hh, out, first, last);
    }
}